// round 13
// baseline (speedup 1.0000x reference)
#include <cuda_runtime.h>
#include <cuda_bf16.h>
#include <cuda_fp16.h>
#include <cstdint>

#define NN 100000
#define EE 1600000
#define HH 128
#define NTILES ((NN + 63) / 64)      // 1563

typedef unsigned long long ull;

// ---- scratch (device globals) ----
static __device__ __half g_a[(size_t)NN * HH];    // ping
static __device__ __half g_b[(size_t)NN * HH];    // pong
static __device__ float  d_dinv[NN];
static __device__ int    d_deg[NN];
static __device__ int    d_rowstart[NN + 1];
static __device__ int    d_cursor[NN];
static __device__ int    d_srcs[EE];
#define LDA 136
static __device__ __nv_bfloat16 d_W1h[128 * LDA], d_W1l[128 * LDA];
static __device__ __half d_W2h[128 * LDA], d_W2l[128 * LDA];

// ---------------------------------------------------------------- CSR build
__global__ void k_zero_deg() {
    int i = blockIdx.x * blockDim.x + threadIdx.x;
    if (i < NN / 4) reinterpret_cast<int4*>(d_deg)[i] = make_int4(0, 0, 0, 0);
}

__global__ void k_count(const int* __restrict__ dst) {
    int i = blockIdx.x * blockDim.x + threadIdx.x;
    if (i >= EE / 4) return;
    int4 d = reinterpret_cast<const int4*>(dst)[i];
    atomicAdd(&d_deg[d.x], 1);
    atomicAdd(&d_deg[d.y], 1);
    atomicAdd(&d_deg[d.z], 1);
    atomicAdd(&d_deg[d.w], 1);
}

__global__ void k_scan() {
    __shared__ int warpsum[32];
    int tid  = threadIdx.x;
    int lane = tid & 31;
    int wid  = tid >> 5;
    int running = 0;
    for (int base = 0; base < NN; base += 4096) {
        int gi = base + tid * 4;
        int4 v = make_int4(0, 0, 0, 0);
        if (gi + 3 < NN) {
            v = *reinterpret_cast<const int4*>(&d_deg[gi]);
        } else {
            if (gi     < NN) v.x = d_deg[gi];
            if (gi + 1 < NN) v.y = d_deg[gi + 1];
            if (gi + 2 < NN) v.z = d_deg[gi + 2];
            if (gi + 3 < NN) v.w = d_deg[gi + 3];
        }
        int t = v.x + v.y + v.z + v.w;
        int inc = t;
#pragma unroll
        for (int off = 1; off < 32; off <<= 1) {
            int n = __shfl_up_sync(0xffffffffu, inc, off);
            if (lane >= off) inc += n;
        }
        if (lane == 31) warpsum[wid] = inc;
        __syncthreads();
        if (wid == 0) {
            int wi = warpsum[lane];
#pragma unroll
            for (int off = 1; off < 32; off <<= 1) {
                int n = __shfl_up_sync(0xffffffffu, wi, off);
                if (lane >= off) wi += n;
            }
            warpsum[lane] = wi;
        }
        __syncthreads();
        int warpoff = (wid > 0) ? warpsum[wid - 1] : 0;
        int excl = running + warpoff + inc - t;
        if (gi < NN) {
            d_rowstart[gi] = excl; d_cursor[gi] = excl;
            d_dinv[gi] = rsqrtf((float)(v.x + 1)); excl += v.x;
        }
        if (gi + 1 < NN) {
            d_rowstart[gi + 1] = excl; d_cursor[gi + 1] = excl;
            d_dinv[gi + 1] = rsqrtf((float)(v.y + 1)); excl += v.y;
        }
        if (gi + 2 < NN) {
            d_rowstart[gi + 2] = excl; d_cursor[gi + 2] = excl;
            d_dinv[gi + 2] = rsqrtf((float)(v.z + 1)); excl += v.z;
        }
        if (gi + 3 < NN) {
            d_rowstart[gi + 3] = excl; d_cursor[gi + 3] = excl;
            d_dinv[gi + 3] = rsqrtf((float)(v.w + 1));
        }
        int tot = warpsum[31];
        __syncthreads();
        running += tot;
    }
    if (tid == 0) d_rowstart[NN] = EE;
}

__global__ void k_scatter(const int* __restrict__ src, const int* __restrict__ dst) {
    int i = blockIdx.x * blockDim.x + threadIdx.x;
    if (i >= EE / 4) return;
    int4 d = reinterpret_cast<const int4*>(dst)[i];
    int4 s = reinterpret_cast<const int4*>(src)[i];
    d_srcs[atomicAdd(&d_cursor[d.x], 1)] = s.x;
    d_srcs[atomicAdd(&d_cursor[d.y], 1)] = s.y;
    d_srcs[atomicAdd(&d_cursor[d.z], 1)] = s.z;
    d_srcs[atomicAdd(&d_cursor[d.w], 1)] = s.w;
}

// ---------------------------------------------------------------- W pre-convert
__global__ void k_prepw_bf16(const float* __restrict__ W,
                             __nv_bfloat16* __restrict__ oh, __nv_bfloat16* __restrict__ ol) {
    int idx = blockIdx.x * blockDim.x + threadIdx.x;
    if (idx >= 128 * 128) return;
    int k = idx >> 7;
    int n = idx & 127;
    float v = W[(size_t)k * HH + n];
    __nv_bfloat16 h = __float2bfloat16_rn(v);
    __nv_bfloat16 l = __float2bfloat16_rn(v - __bfloat162float(h));
    oh[n * LDA + k] = h;
    ol[n * LDA + k] = l;
}

__global__ void k_prepw_f16(const float* __restrict__ W,
                            __half* __restrict__ oh, __half* __restrict__ ol) {
    int idx = blockIdx.x * blockDim.x + threadIdx.x;
    if (idx >= 128 * 128) return;
    int k = idx >> 7;
    int n = idx & 127;
    float v = W[(size_t)k * HH + n];
    __half h = __float2half_rn(v);
    __half l = __float2half_rn(v - __half2float(h));
    oh[n * LDA + k] = h;
    ol[n * LDA + k] = l;
}

// ---------------------------------------------------------------- mma utils
__device__ __forceinline__ uint32_t smem_u32(const void* p) {
    uint32_t a;
    asm("{ .reg .u64 t; cvta.to.shared.u64 t, %1; cvt.u32.u64 %0, t; }" : "=r"(a) : "l"(p));
    return a;
}
__device__ __forceinline__ void ldsm4(uint32_t* r, uint32_t addr) {
    asm volatile("ldmatrix.sync.aligned.m8n8.x4.shared.b16 {%0,%1,%2,%3}, [%4];"
                 : "=r"(r[0]), "=r"(r[1]), "=r"(r[2]), "=r"(r[3]) : "r"(addr));
}
__device__ __forceinline__ void mma_bf16(float* d, const uint32_t* a, const uint32_t* b) {
    asm volatile(
        "mma.sync.aligned.m16n8k16.row.col.f32.bf16.bf16.f32 "
        "{%0,%1,%2,%3}, {%4,%5,%6,%7}, {%8,%9}, {%0,%1,%2,%3};"
        : "+f"(d[0]), "+f"(d[1]), "+f"(d[2]), "+f"(d[3])
        : "r"(a[0]), "r"(a[1]), "r"(a[2]), "r"(a[3]), "r"(b[0]), "r"(b[1]));
}
__device__ __forceinline__ void mma_f16(float* d, const uint32_t* a, const uint32_t* b) {
    asm volatile(
        "mma.sync.aligned.m16n8k16.row.col.f32.f16.f16.f32 "
        "{%0,%1,%2,%3}, {%4,%5,%6,%7}, {%8,%9}, {%0,%1,%2,%3};"
        : "+f"(d[0]), "+f"(d[1]), "+f"(d[2]), "+f"(d[3])
        : "r"(a[0]), "r"(a[1]), "r"(a[2]), "r"(a[3]), "r"(b[0]), "r"(b[1]));
}
__device__ __forceinline__ uint32_t pack_hi(float x, float y, uint32_t& lo) {
    __nv_bfloat16 h0 = __float2bfloat16_rn(x);
    __nv_bfloat16 h1 = __float2bfloat16_rn(y);
    __nv_bfloat16 l0 = __float2bfloat16_rn(x - __bfloat162float(h0));
    __nv_bfloat16 l1 = __float2bfloat16_rn(y - __bfloat162float(h1));
    lo = (uint32_t)__bfloat16_as_ushort(l0) | ((uint32_t)__bfloat16_as_ushort(l1) << 16);
    return (uint32_t)__bfloat16_as_ushort(h0) | ((uint32_t)__bfloat16_as_ushort(h1) << 16);
}

#define A_TILE_B (64 * LDA * 2)
#define B_TILE_B (128 * LDA * 2)

// ---------------------------------------------------------------- GEMM layer 1
#define SM1_AH 0
#define SM1_AL (A_TILE_B)
#define SM1_BH (2 * A_TILE_B)
#define SM1_BL (2 * A_TILE_B + B_TILE_B)
#define SM1_TOTAL (2 * A_TILE_B + 2 * B_TILE_B)

__global__ void __launch_bounds__(256, 2)
k_gemm1(const float* __restrict__ xf32,
        const __nv_bfloat16* __restrict__ Wh, const __nv_bfloat16* __restrict__ Wl) {
    extern __shared__ __align__(16) char smem[];
    uint32_t sb = smem_u32(smem);
    int tid  = threadIdx.x;
    int wid  = tid >> 5;
    int lane = tid & 31;
    int row0 = blockIdx.x * 64;

    for (int idx = tid; idx < 64 * 64; idx += 256) {
        int r  = idx >> 6;
        int kp = idx & 63;
        int grow = row0 + r;
        float2 v = make_float2(0.f, 0.f);
        if (grow < NN)
            v = *reinterpret_cast<const float2*>(xf32 + (size_t)grow * HH + kp * 2);
        uint32_t lo, hi = pack_hi(v.x, v.y, lo);
        uint32_t off = (uint32_t)(r * LDA + kp * 2) * 2;
        *reinterpret_cast<uint32_t*>(smem + SM1_AH + off) = hi;
        *reinterpret_cast<uint32_t*>(smem + SM1_AL + off) = lo;
    }
    {
        const uint4* gh = reinterpret_cast<const uint4*>(Wh);
        const uint4* gl = reinterpret_cast<const uint4*>(Wl);
        uint4* shv = reinterpret_cast<uint4*>(smem + SM1_BH);
        uint4* slv = reinterpret_cast<uint4*>(smem + SM1_BL);
        for (int i = tid; i < B_TILE_B / 16; i += 256) {
            shv[i] = gh[i];
            slv[i] = gl[i];
        }
    }
    __syncthreads();

    int wr = wid & 3;
    int wc = wid >> 2;
    int m0 = wr * 16;
    float acc[8][4];
#pragma unroll
    for (int i = 0; i < 8; i++)
#pragma unroll
        for (int j = 0; j < 4; j++) acc[i][j] = 0.f;

    uint32_t a_off = (uint32_t)((m0 + (lane & 15)) * LDA + ((lane >> 4) << 3)) * 2;
    uint32_t b_off = (uint32_t)(((lane & 7) + ((lane >> 1) & 8)) * LDA + (lane & 8)) * 2;

#pragma unroll
    for (int ks = 0; ks < 8; ks++) {
        int k0 = ks * 16;
        uint32_t ah[4], al[4];
        ldsm4(ah, sb + SM1_AH + a_off + k0 * 2);
        ldsm4(al, sb + SM1_AL + a_off + k0 * 2);
#pragma unroll
        for (int np = 0; np < 4; np++) {
            uint32_t bh[4], bl[4];
            uint32_t bo = (uint32_t)((wc * 64 + np * 16) * LDA + k0) * 2 + b_off;
            ldsm4(bh, sb + SM1_BH + bo);
            ldsm4(bl, sb + SM1_BL + bo);
            mma_bf16(acc[2 * np],     ah, bh);
            mma_bf16(acc[2 * np + 1], ah, bh + 2);
            mma_bf16(acc[2 * np],     al, bh);
            mma_bf16(acc[2 * np + 1], al, bh + 2);
            mma_bf16(acc[2 * np],     ah, bl);
            mma_bf16(acc[2 * np + 1], ah, bl + 2);
        }
    }

    int r0 = row0 + m0 + (lane >> 2);
    int r1 = r0 + 8;
    int c0 = wc * 64 + (lane & 3) * 2;
#pragma unroll
    for (int nt = 0; nt < 8; nt++) {
        int col = c0 + nt * 8;
        if (r0 < NN)
            *reinterpret_cast<__half2*>(&g_a[(size_t)r0 * HH + col]) =
                __floats2half2_rn(acc[nt][0], acc[nt][1]);
        if (r1 < NN)
            *reinterpret_cast<__half2*>(&g_a[(size_t)r1 * HH + col]) =
                __floats2half2_rn(acc[nt][2], acc[nt][3]);
    }
}

// ---------------------------------------------------------------- fused agg+GEMM
// Persistent. For each 64-row tile: stage A = relu( dinv*(agg of g_in) + b + x ),
// computed in-register from CSR gathers, written to smem; then 2-term f16 mma
// with W2; epilogue writes g_out scaled by dinv[row].
#define SM2_A0 0
#define SM2_A1 (A_TILE_B)
#define SM2_BH (2 * A_TILE_B)
#define SM2_BL (2 * A_TILE_B + B_TILE_B)
#define SM2_TOTAL (2 * A_TILE_B + 2 * B_TILE_B)

__global__ void __launch_bounds__(256, 2)
k_fused(const __half* __restrict__ g_in, __half* __restrict__ g_out,
        const float* __restrict__ x, const float* __restrict__ bias,
        const __half* __restrict__ Wh, const __half* __restrict__ Wl,
        int pre_scaled) {
    extern __shared__ __align__(16) char smem[];
    uint32_t sb = smem_u32(smem);
    int tid  = threadIdx.x;
    int wid  = tid >> 5;
    int lane = tid & 31;

    // stage B once
    {
        const uint4* gh = reinterpret_cast<const uint4*>(Wh);
        const uint4* gl = reinterpret_cast<const uint4*>(Wl);
        uint4* shv = reinterpret_cast<uint4*>(smem + SM2_BH);
        uint4* slv = reinterpret_cast<uint4*>(smem + SM2_BL);
        for (int i = tid; i < B_TILE_B / 16; i += 256) {
            shv[i] = gh[i];
            slv[i] = gl[i];
        }
    }

    float4 bb = *reinterpret_cast<const float4*>(bias + lane * 4);
    const uint2* g2 = reinterpret_cast<const uint2*>(g_in);

    // stage-agg: warp wid computes rows wid*8..wid*8+7 of the tile
    auto stageAgg = [&](int tile, int bufsel) {
        char* dstb = smem + (bufsel ? SM2_A1 : SM2_A0);
        int rbase = wid * 8;
        int row0t = tile * 64;
#pragma unroll 1
        for (int rr = 0; rr < 8; rr++) {
            int node = row0t + rbase + rr;
            if (node >= NN) break;
            float dv = d_dinv[node];
            size_t base = (size_t)node * 32;
            uint2 sv = g2[base + lane];
            float2 f0 = __half22float2(*reinterpret_cast<__half2*>(&sv.x));
            float2 f1 = __half22float2(*reinterpret_cast<__half2*>(&sv.y));
            float selfs = pre_scaled ? 1.f : dv;
            float4 acc = make_float4(f0.x * selfs, f0.y * selfs, f1.x * selfs, f1.y * selfs);
            int e0 = d_rowstart[node];
            int e1 = d_rowstart[node + 1];
            int e = e0;
            if (pre_scaled) {
                for (; e + 4 <= e1; e += 4) {
                    int s0 = d_srcs[e], s1 = d_srcs[e + 1], s2 = d_srcs[e + 2], s3 = d_srcs[e + 3];
                    uint2 v0 = g2[(size_t)s0 * 32 + lane];
                    uint2 v1 = g2[(size_t)s1 * 32 + lane];
                    uint2 v2 = g2[(size_t)s2 * 32 + lane];
                    uint2 v3 = g2[(size_t)s3 * 32 + lane];
#define ACC4(v) { \
                    float2 a0 = __half22float2(*reinterpret_cast<__half2*>(&(v).x)); \
                    float2 a1 = __half22float2(*reinterpret_cast<__half2*>(&(v).y)); \
                    acc.x += a0.x; acc.y += a0.y; acc.z += a1.x; acc.w += a1.y; }
                    ACC4(v0) ACC4(v1) ACC4(v2) ACC4(v3)
                }
                for (; e < e1; ++e) {
                    uint2 v = g2[(size_t)d_srcs[e] * 32 + lane];
                    ACC4(v)
                }
#undef ACC4
            } else {
                for (; e + 4 <= e1; e += 4) {
                    int s0 = d_srcs[e], s1 = d_srcs[e + 1], s2 = d_srcs[e + 2], s3 = d_srcs[e + 3];
                    float d0 = d_dinv[s0], d1 = d_dinv[s1], d2 = d_dinv[s2], d3 = d_dinv[s3];
                    uint2 v0 = g2[(size_t)s0 * 32 + lane];
                    uint2 v1 = g2[(size_t)s1 * 32 + lane];
                    uint2 v2 = g2[(size_t)s2 * 32 + lane];
                    uint2 v3 = g2[(size_t)s3 * 32 + lane];
#define ACCD(v, d) { \
                    float2 a0 = __half22float2(*reinterpret_cast<__half2*>(&(v).x)); \
                    float2 a1 = __half22float2(*reinterpret_cast<__half2*>(&(v).y)); \
                    acc.x = fmaf((d), a0.x, acc.x); acc.y = fmaf((d), a0.y, acc.y); \
                    acc.z = fmaf((d), a1.x, acc.z); acc.w = fmaf((d), a1.y, acc.w); }
                    ACCD(v0, d0) ACCD(v1, d1) ACCD(v2, d2) ACCD(v3, d3)
                }
                for (; e < e1; ++e) {
                    int s = d_srcs[e];
                    float d = d_dinv[s];
                    uint2 v = g2[(size_t)s * 32 + lane];
                    ACCD(v, d)
                }
#undef ACCD
            }
            float4 xv = *reinterpret_cast<const float4*>(x + (size_t)node * HH + lane * 4);
            float4 o;
            o.x = fmaxf(fmaf(dv, acc.x, bb.x + xv.x), 0.f);
            o.y = fmaxf(fmaf(dv, acc.y, bb.y + xv.y), 0.f);
            o.z = fmaxf(fmaf(dv, acc.z, bb.z + xv.z), 0.f);
            o.w = fmaxf(fmaf(dv, acc.w, bb.w + xv.w), 0.f);
            uint2 pk;
            *reinterpret_cast<__half2*>(&pk.x) = __floats2half2_rn(o.x, o.y);
            *reinterpret_cast<__half2*>(&pk.y) = __floats2half2_rn(o.z, o.w);
            *reinterpret_cast<uint2*>(dstb + (uint32_t)((rbase + rr) * LDA + lane * 4) * 2) = pk;
        }
    };

    int wr = wid & 3;
    int wc = wid >> 2;
    int m0 = wr * 16;
    uint32_t a_off = (uint32_t)((m0 + (lane & 15)) * LDA + ((lane >> 4) << 3)) * 2;
    uint32_t b_off = (uint32_t)(((lane & 7) + ((lane >> 1) & 8)) * LDA + (lane & 8)) * 2;

    int t0 = blockIdx.x;
    if (t0 < NTILES) stageAgg(t0, 0);
    __syncthreads();

    int buf = 0;
    for (int t = t0; t < NTILES; t += gridDim.x, buf ^= 1) {
        // mma on current buffer (operands ready)
        uint32_t abase = sb + (buf ? SM2_A1 : SM2_A0) + a_off;
        float acc[8][4];
#pragma unroll
        for (int i = 0; i < 8; i++)
#pragma unroll
            for (int j = 0; j < 4; j++) acc[i][j] = 0.f;

#pragma unroll
        for (int ks = 0; ks < 8; ks++) {
            int k0 = ks * 16;
            uint32_t a[4];
            ldsm4(a, abase + k0 * 2);
#pragma unroll
            for (int np = 0; np < 4; np++) {
                uint32_t bh[4], bl[4];
                uint32_t bo = (uint32_t)((wc * 64 + np * 16) * LDA + k0) * 2 + b_off;
                ldsm4(bh, sb + SM2_BH + bo);
                ldsm4(bl, sb + SM2_BL + bo);
                mma_f16(acc[2 * np],     a, bh);
                mma_f16(acc[2 * np + 1], a, bh + 2);
                mma_f16(acc[2 * np],     a, bl);
                mma_f16(acc[2 * np + 1], a, bl + 2);
            }
        }

        // epilogue: scale by dinv[row], write g_out
        {
            int row0 = t * 64;
            int r0 = row0 + m0 + (lane >> 2);
            int r1 = r0 + 8;
            float s0 = (r0 < NN) ? d_dinv[r0] : 0.f;
            float s1 = (r1 < NN) ? d_dinv[r1] : 0.f;
            int c0 = wc * 64 + (lane & 3) * 2;
#pragma unroll
            for (int nt = 0; nt < 8; nt++) {
                int col = c0 + nt * 8;
                if (r0 < NN)
                    *reinterpret_cast<__half2*>(&g_out[(size_t)r0 * HH + col]) =
                        __floats2half2_rn(acc[nt][0] * s0, acc[nt][1] * s0);
                if (r1 < NN)
                    *reinterpret_cast<__half2*>(&g_out[(size_t)r1 * HH + col]) =
                        __floats2half2_rn(acc[nt][2] * s1, acc[nt][3] * s1);
            }
        }

        // stage next tile into other buffer
        int nxt = t + gridDim.x;
        if (nxt < NTILES) stageAgg(nxt, buf ^ 1);
        __syncthreads();
    }
}

// ---------------------------------------------------------------- final aggregation
__global__ void k_agg(const __half* __restrict__ g_in,
                      const float* __restrict__ x, const float* __restrict__ bias,
                      float* __restrict__ outp) {
    int gtid = blockIdx.x * blockDim.x + threadIdx.x;
    int node = gtid >> 5;
    int lane = gtid & 31;
    if (node >= NN) return;

    const uint2* g2 = reinterpret_cast<const uint2*>(g_in);
    size_t base = (size_t)node * 32;
    float dv = d_dinv[node];

    uint2 sv = g2[base + lane];
    float2 f0 = __half22float2(*reinterpret_cast<__half2*>(&sv.x));
    float2 f1 = __half22float2(*reinterpret_cast<__half2*>(&sv.y));
    float4 acc = make_float4(f0.x, f0.y, f1.x, f1.y);   // pre-scaled input

    int e0 = d_rowstart[node];
    int e1 = d_rowstart[node + 1];
    int e = e0;
    for (; e + 4 <= e1; e += 4) {
        int s0 = d_srcs[e], s1 = d_srcs[e + 1], s2 = d_srcs[e + 2], s3 = d_srcs[e + 3];
        uint2 v0 = g2[(size_t)s0 * 32 + lane];
        uint2 v1 = g2[(size_t)s1 * 32 + lane];
        uint2 v2 = g2[(size_t)s2 * 32 + lane];
        uint2 v3 = g2[(size_t)s3 * 32 + lane];
#define ACC4(v) { \
        float2 a0 = __half22float2(*reinterpret_cast<__half2*>(&(v).x)); \
        float2 a1 = __half22float2(*reinterpret_cast<__half2*>(&(v).y)); \
        acc.x += a0.x; acc.y += a0.y; acc.z += a1.x; acc.w += a1.y; }
        ACC4(v0) ACC4(v1) ACC4(v2) ACC4(v3)
    }
    for (; e < e1; ++e) {
        uint2 v = g2[(size_t)d_srcs[e] * 32 + lane];
        ACC4(v)
    }
#undef ACC4
    size_t cbase = (size_t)node * HH + lane * 4;
    float4 bbv = *reinterpret_cast<const float4*>(bias + lane * 4);
    float4 xv  = *reinterpret_cast<const float4*>(x + cbase);
    float4 o;
    o.x = fmaf(dv, acc.x, bbv.x + xv.x);
    o.y = fmaf(dv, acc.y, bbv.y + xv.y);
    o.z = fmaf(dv, acc.z, bbv.z + xv.z);
    o.w = fmaf(dv, acc.w, bbv.w + xv.w);
    *reinterpret_cast<float4*>(outp + cbase) = o;
}

// ---------------------------------------------------------------- launch
extern "C" void kernel_launch(void* const* d_in, const int* in_sizes, int n_in,
                              void* d_out, int out_size) {
    const float* x   = (const float*)d_in[0];
    const int*   src = (const int*)  d_in[1];
    const int*   dst = (const int*)  d_in[2];
    const float* W1  = (const float*)d_in[3];
    const float* b1  = (const float*)d_in[4];
    const float* W2  = (const float*)d_in[5];
    const float* b2  = (const float*)d_in[6];
    float* out = (float*)d_out;

    (void)in_sizes; (void)n_in; (void)out_size;

    static int inited = 0;
    static cudaStream_t s1;
    static cudaEvent_t evFork, evJoin;
    if (!inited) {
        cudaFuncSetAttribute(k_gemm1, cudaFuncAttributeMaxDynamicSharedMemorySize, SM1_TOTAL);
        cudaFuncSetAttribute(k_fused, cudaFuncAttributeMaxDynamicSharedMemorySize, SM2_TOTAL);
        cudaStreamCreateWithFlags(&s1, cudaStreamNonBlocking);
        cudaEventCreateWithFlags(&evFork, cudaEventDisableTiming);
        cudaEventCreateWithFlags(&evJoin, cudaEventDisableTiming);
        inited = 1;
    }

    __nv_bfloat16 *w1h, *w1l;
    __half *w2h, *w2l, *ga, *gb;
    cudaGetSymbolAddress((void**)&w1h, d_W1h);
    cudaGetSymbolAddress((void**)&w1l, d_W1l);
    cudaGetSymbolAddress((void**)&w2h, d_W2h);
    cudaGetSymbolAddress((void**)&w2l, d_W2l);
    cudaGetSymbolAddress((void**)&ga, g_a);
    cudaGetSymbolAddress((void**)&gb, g_b);

    const int fused_grid = 296;               // persistent: 2 CTAs x 148 SMs
    const int agg_grid = (NN * 32 + 255) / 256;

    // Fork: CSR build + W2 prep on s1; W1 prep + GEMM1 on main.
    cudaEventRecord(evFork, 0);
    cudaStreamWaitEvent(s1, evFork, 0);

    k_zero_deg<<<(NN / 4 + 255) / 256, 256, 0, s1>>>();
    k_count   <<<(EE / 4 + 255) / 256, 256, 0, s1>>>(dst);
    k_scan    <<<1, 1024, 0, s1>>>();
    k_scatter <<<(EE / 4 + 255) / 256, 256, 0, s1>>>(src, dst);
    k_prepw_f16<<<64, 256, 0, s1>>>(W2, w2h, w2l);
    cudaEventRecord(evJoin, s1);

    k_prepw_bf16<<<64, 256>>>(W1, w1h, w1l);
    k_gemm1<<<NTILES, 256, SM1_TOTAL>>>(x, w1h, w1l);   // overlaps CSR

    cudaStreamWaitEvent(0, evJoin, 0);

    // fused layer-1 agg + layer-2 gemm: g_a (unscaled) -> g_b (scaled)
    k_fused<<<fused_grid, 256, SM2_TOTAL>>>(ga, gb, x, b1, w2h, w2l, /*pre_scaled=*/0);
    // fused layer-2 agg + layer-3 gemm: g_b (scaled) -> g_a (scaled)
    k_fused<<<fused_grid, 256, SM2_TOTAL>>>(gb, ga, x, b2, w2h, w2l, /*pre_scaled=*/1);
    // final layer-3 aggregation -> out
    k_agg<<<agg_grid, 256>>>(ga, x, b2, out);
}

// round 14
// speedup vs baseline: 1.3081x; 1.3081x over previous
#include <cuda_runtime.h>
#include <cuda_bf16.h>
#include <cuda_fp16.h>
#include <cstdint>

#define NN 100000
#define EE 1600000
#define HH 128
#define NTILES ((NN + 63) / 64)      // 1563

typedef unsigned long long ull;

// ---- scratch (device globals) ----
static __device__ __half g_hb[(size_t)NN * HH];   // GEMM output, fp16
static __device__ __half h_hb[(size_t)NN * HH];   // layer activations (relu'd), fp16
static __device__ float  d_dinv[NN];
static __device__ int    d_deg[NN];
static __device__ int    d_rowstart[NN + 1];
static __device__ int    d_cursor[NN];
static __device__ int    d_srcs[EE];
#define LDA 136
static __device__ __nv_bfloat16 d_W1h[128 * LDA], d_W1l[128 * LDA];
static __device__ __half d_W2h[128 * LDA], d_W2l[128 * LDA];

// ---------------------------------------------------------------- CSR build
__global__ void k_zero_deg() {
    int i = blockIdx.x * blockDim.x + threadIdx.x;
    if (i < NN / 4) reinterpret_cast<int4*>(d_deg)[i] = make_int4(0, 0, 0, 0);
}

__global__ void k_count(const int* __restrict__ dst) {
    int i = blockIdx.x * blockDim.x + threadIdx.x;
    if (i >= EE / 4) return;
    int4 d = reinterpret_cast<const int4*>(dst)[i];
    atomicAdd(&d_deg[d.x], 1);
    atomicAdd(&d_deg[d.y], 1);
    atomicAdd(&d_deg[d.z], 1);
    atomicAdd(&d_deg[d.w], 1);
}

__global__ void k_scan() {
    __shared__ int warpsum[32];
    int tid  = threadIdx.x;
    int lane = tid & 31;
    int wid  = tid >> 5;
    int running = 0;
    for (int base = 0; base < NN; base += 4096) {
        int gi = base + tid * 4;
        int4 v = make_int4(0, 0, 0, 0);
        if (gi + 3 < NN) {
            v = *reinterpret_cast<const int4*>(&d_deg[gi]);
        } else {
            if (gi     < NN) v.x = d_deg[gi];
            if (gi + 1 < NN) v.y = d_deg[gi + 1];
            if (gi + 2 < NN) v.z = d_deg[gi + 2];
            if (gi + 3 < NN) v.w = d_deg[gi + 3];
        }
        int t = v.x + v.y + v.z + v.w;
        int inc = t;
#pragma unroll
        for (int off = 1; off < 32; off <<= 1) {
            int n = __shfl_up_sync(0xffffffffu, inc, off);
            if (lane >= off) inc += n;
        }
        if (lane == 31) warpsum[wid] = inc;
        __syncthreads();
        if (wid == 0) {
            int wi = warpsum[lane];
#pragma unroll
            for (int off = 1; off < 32; off <<= 1) {
                int n = __shfl_up_sync(0xffffffffu, wi, off);
                if (lane >= off) wi += n;
            }
            warpsum[lane] = wi;
        }
        __syncthreads();
        int warpoff = (wid > 0) ? warpsum[wid - 1] : 0;
        int excl = running + warpoff + inc - t;
        if (gi < NN) {
            d_rowstart[gi] = excl; d_cursor[gi] = excl;
            d_dinv[gi] = rsqrtf((float)(v.x + 1)); excl += v.x;
        }
        if (gi + 1 < NN) {
            d_rowstart[gi + 1] = excl; d_cursor[gi + 1] = excl;
            d_dinv[gi + 1] = rsqrtf((float)(v.y + 1)); excl += v.y;
        }
        if (gi + 2 < NN) {
            d_rowstart[gi + 2] = excl; d_cursor[gi + 2] = excl;
            d_dinv[gi + 2] = rsqrtf((float)(v.z + 1)); excl += v.z;
        }
        if (gi + 3 < NN) {
            d_rowstart[gi + 3] = excl; d_cursor[gi + 3] = excl;
            d_dinv[gi + 3] = rsqrtf((float)(v.w + 1));
        }
        int tot = warpsum[31];
        __syncthreads();
        running += tot;
    }
    if (tid == 0) d_rowstart[NN] = EE;
}

__global__ void k_scatter(const int* __restrict__ src, const int* __restrict__ dst) {
    int i = blockIdx.x * blockDim.x + threadIdx.x;
    if (i >= EE / 4) return;
    int4 d = reinterpret_cast<const int4*>(dst)[i];
    int4 s = reinterpret_cast<const int4*>(src)[i];
    d_srcs[atomicAdd(&d_cursor[d.x], 1)] = s.x;
    d_srcs[atomicAdd(&d_cursor[d.y], 1)] = s.y;
    d_srcs[atomicAdd(&d_cursor[d.z], 1)] = s.z;
    d_srcs[atomicAdd(&d_cursor[d.w], 1)] = s.w;
}

// ---------------------------------------------------------------- W pre-convert
__global__ void k_prepw_bf16(const float* __restrict__ W,
                             __nv_bfloat16* __restrict__ oh, __nv_bfloat16* __restrict__ ol) {
    int idx = blockIdx.x * blockDim.x + threadIdx.x;
    if (idx >= 128 * 128) return;
    int k = idx >> 7;
    int n = idx & 127;
    float v = W[(size_t)k * HH + n];
    __nv_bfloat16 h = __float2bfloat16_rn(v);
    __nv_bfloat16 l = __float2bfloat16_rn(v - __bfloat162float(h));
    oh[n * LDA + k] = h;
    ol[n * LDA + k] = l;
}

__global__ void k_prepw_f16(const float* __restrict__ W,
                            __half* __restrict__ oh, __half* __restrict__ ol) {
    int idx = blockIdx.x * blockDim.x + threadIdx.x;
    if (idx >= 128 * 128) return;
    int k = idx >> 7;
    int n = idx & 127;
    float v = W[(size_t)k * HH + n];
    __half h = __float2half_rn(v);
    __half l = __float2half_rn(v - __half2float(h));
    oh[n * LDA + k] = h;
    ol[n * LDA + k] = l;
}

// ---------------------------------------------------------------- mma utils
__device__ __forceinline__ uint32_t smem_u32(const void* p) {
    uint32_t a;
    asm("{ .reg .u64 t; cvta.to.shared.u64 t, %1; cvt.u32.u64 %0, t; }" : "=r"(a) : "l"(p));
    return a;
}
__device__ __forceinline__ void ldsm4(uint32_t* r, uint32_t addr) {
    asm volatile("ldmatrix.sync.aligned.m8n8.x4.shared.b16 {%0,%1,%2,%3}, [%4];"
                 : "=r"(r[0]), "=r"(r[1]), "=r"(r[2]), "=r"(r[3]) : "r"(addr));
}
__device__ __forceinline__ void mma_bf16(float* d, const uint32_t* a, const uint32_t* b) {
    asm volatile(
        "mma.sync.aligned.m16n8k16.row.col.f32.bf16.bf16.f32 "
        "{%0,%1,%2,%3}, {%4,%5,%6,%7}, {%8,%9}, {%0,%1,%2,%3};"
        : "+f"(d[0]), "+f"(d[1]), "+f"(d[2]), "+f"(d[3])
        : "r"(a[0]), "r"(a[1]), "r"(a[2]), "r"(a[3]), "r"(b[0]), "r"(b[1]));
}
__device__ __forceinline__ void mma_f16(float* d, const uint32_t* a, const uint32_t* b) {
    asm volatile(
        "mma.sync.aligned.m16n8k16.row.col.f32.f16.f16.f32 "
        "{%0,%1,%2,%3}, {%4,%5,%6,%7}, {%8,%9}, {%0,%1,%2,%3};"
        : "+f"(d[0]), "+f"(d[1]), "+f"(d[2]), "+f"(d[3])
        : "r"(a[0]), "r"(a[1]), "r"(a[2]), "r"(a[3]), "r"(b[0]), "r"(b[1]));
}
__device__ __forceinline__ uint32_t pack_hi(float x, float y, uint32_t& lo) {
    __nv_bfloat16 h0 = __float2bfloat16_rn(x);
    __nv_bfloat16 h1 = __float2bfloat16_rn(y);
    __nv_bfloat16 l0 = __float2bfloat16_rn(x - __bfloat162float(h0));
    __nv_bfloat16 l1 = __float2bfloat16_rn(y - __bfloat162float(h1));
    lo = (uint32_t)__bfloat16_as_ushort(l0) | ((uint32_t)__bfloat16_as_ushort(l1) << 16);
    return (uint32_t)__bfloat16_as_ushort(h0) | ((uint32_t)__bfloat16_as_ushort(h1) << 16);
}

#define A_TILE_B (64 * LDA * 2)
#define B_TILE_B (128 * LDA * 2)

// ---------------------------------------------------------------- GEMM layer 1
#define SM1_AH 0
#define SM1_AL (A_TILE_B)
#define SM1_BH (2 * A_TILE_B)
#define SM1_BL (2 * A_TILE_B + B_TILE_B)
#define SM1_TOTAL (2 * A_TILE_B + 2 * B_TILE_B)

__global__ void __launch_bounds__(256, 2)
k_gemm1(const float* __restrict__ xf32,
        const __nv_bfloat16* __restrict__ Wh, const __nv_bfloat16* __restrict__ Wl) {
    extern __shared__ __align__(16) char smem[];
    uint32_t sb = smem_u32(smem);
    int tid  = threadIdx.x;
    int wid  = tid >> 5;
    int lane = tid & 31;
    int row0 = blockIdx.x * 64;

    for (int idx = tid; idx < 64 * 64; idx += 256) {
        int r  = idx >> 6;
        int kp = idx & 63;
        int grow = row0 + r;
        float2 v = make_float2(0.f, 0.f);
        if (grow < NN)
            v = *reinterpret_cast<const float2*>(xf32 + (size_t)grow * HH + kp * 2);
        uint32_t lo, hi = pack_hi(v.x, v.y, lo);
        uint32_t off = (uint32_t)(r * LDA + kp * 2) * 2;
        *reinterpret_cast<uint32_t*>(smem + SM1_AH + off) = hi;
        *reinterpret_cast<uint32_t*>(smem + SM1_AL + off) = lo;
    }
    {
        const uint4* gh = reinterpret_cast<const uint4*>(Wh);
        const uint4* gl = reinterpret_cast<const uint4*>(Wl);
        uint4* shv = reinterpret_cast<uint4*>(smem + SM1_BH);
        uint4* slv = reinterpret_cast<uint4*>(smem + SM1_BL);
        for (int i = tid; i < B_TILE_B / 16; i += 256) {
            shv[i] = gh[i];
            slv[i] = gl[i];
        }
    }
    __syncthreads();

    int wr = wid & 3;
    int wc = wid >> 2;
    int m0 = wr * 16;
    float acc[8][4];
#pragma unroll
    for (int i = 0; i < 8; i++)
#pragma unroll
        for (int j = 0; j < 4; j++) acc[i][j] = 0.f;

    uint32_t a_off = (uint32_t)((m0 + (lane & 15)) * LDA + ((lane >> 4) << 3)) * 2;
    uint32_t b_off = (uint32_t)(((lane & 7) + ((lane >> 1) & 8)) * LDA + (lane & 8)) * 2;

#pragma unroll
    for (int ks = 0; ks < 8; ks++) {
        int k0 = ks * 16;
        uint32_t ah[4], al[4];
        ldsm4(ah, sb + SM1_AH + a_off + k0 * 2);
        ldsm4(al, sb + SM1_AL + a_off + k0 * 2);
#pragma unroll
        for (int np = 0; np < 4; np++) {
            uint32_t bh[4], bl[4];
            uint32_t bo = (uint32_t)((wc * 64 + np * 16) * LDA + k0) * 2 + b_off;
            ldsm4(bh, sb + SM1_BH + bo);
            ldsm4(bl, sb + SM1_BL + bo);
            mma_bf16(acc[2 * np],     ah, bh);
            mma_bf16(acc[2 * np + 1], ah, bh + 2);
            mma_bf16(acc[2 * np],     al, bh);
            mma_bf16(acc[2 * np + 1], al, bh + 2);
            mma_bf16(acc[2 * np],     ah, bl);
            mma_bf16(acc[2 * np + 1], ah, bl + 2);
        }
    }

    int r0 = row0 + m0 + (lane >> 2);
    int r1 = r0 + 8;
    int c0 = wc * 64 + (lane & 3) * 2;
#pragma unroll
    for (int nt = 0; nt < 8; nt++) {
        int col = c0 + nt * 8;
        if (r0 < NN)
            *reinterpret_cast<__half2*>(&g_hb[(size_t)r0 * HH + col]) =
                __floats2half2_rn(acc[nt][0], acc[nt][1]);
        if (r1 < NN)
            *reinterpret_cast<__half2*>(&g_hb[(size_t)r1 * HH + col]) =
                __floats2half2_rn(acc[nt][2], acc[nt][3]);
    }
}

// ---------------------------------------------------------------- GEMM 2/3
#define SM2_A0 0
#define SM2_A1 (A_TILE_B)
#define SM2_BH (2 * A_TILE_B)
#define SM2_BL (2 * A_TILE_B + B_TILE_B)
#define SM2_TOTAL (2 * A_TILE_B + 2 * B_TILE_B)

__global__ void __launch_bounds__(256, 2)
k_gemm23(const __half* __restrict__ Wh, const __half* __restrict__ Wl) {
    extern __shared__ __align__(16) char smem[];
    uint32_t sb = smem_u32(smem);
    int tid  = threadIdx.x;
    int wid  = tid >> 5;
    int lane = tid & 31;

    {
        const uint4* gh = reinterpret_cast<const uint4*>(Wh);
        const uint4* gl = reinterpret_cast<const uint4*>(Wl);
        uint4* shv = reinterpret_cast<uint4*>(smem + SM2_BH);
        uint4* slv = reinterpret_cast<uint4*>(smem + SM2_BL);
        for (int i = tid; i < B_TILE_B / 16; i += 256) {
            shv[i] = gh[i];
            slv[i] = gl[i];
        }
    }

    auto stageA = [&](int tile, int bufsel) {
        int row0 = tile * 64;
        char* dstb = smem + (bufsel ? SM2_A1 : SM2_A0);
        const __half* A16 = (const __half*)h_hb;
        for (int idx = tid; idx < 64 * 32; idx += 256) {
            int r  = idx >> 5;
            int k4 = (idx & 31) * 4;
            int grow = row0 + r;
            uint2 v = make_uint2(0u, 0u);
            if (grow < NN)
                v = *reinterpret_cast<const uint2*>(A16 + (size_t)grow * HH + k4);
            *reinterpret_cast<uint2*>(dstb + (uint32_t)(r * LDA + k4) * 2) = v;
        }
    };

    int wr = wid & 3;
    int wc = wid >> 2;
    int m0 = wr * 16;
    uint32_t a_off = (uint32_t)((m0 + (lane & 15)) * LDA + ((lane >> 4) << 3)) * 2;
    uint32_t b_off = (uint32_t)(((lane & 7) + ((lane >> 1) & 8)) * LDA + (lane & 8)) * 2;

    int t0 = blockIdx.x;
    if (t0 < NTILES) stageA(t0, 0);
    __syncthreads();

    int buf = 0;
    for (int t = t0; t < NTILES; t += gridDim.x, buf ^= 1) {
        int nxt = t + gridDim.x;
        if (nxt < NTILES) stageA(nxt, buf ^ 1);

        uint32_t abase = sb + (buf ? SM2_A1 : SM2_A0) + a_off;
        float acc[8][4];
#pragma unroll
        for (int i = 0; i < 8; i++)
#pragma unroll
            for (int j = 0; j < 4; j++) acc[i][j] = 0.f;

#pragma unroll
        for (int ks = 0; ks < 8; ks++) {
            int k0 = ks * 16;
            uint32_t a[4];
            ldsm4(a, abase + k0 * 2);
#pragma unroll
            for (int np = 0; np < 4; np++) {
                uint32_t bh[4], bl[4];
                uint32_t bo = (uint32_t)((wc * 64 + np * 16) * LDA + k0) * 2 + b_off;
                ldsm4(bh, sb + SM2_BH + bo);
                ldsm4(bl, sb + SM2_BL + bo);
                mma_f16(acc[2 * np],     a, bh);
                mma_f16(acc[2 * np + 1], a, bh + 2);
                mma_f16(acc[2 * np],     a, bl);
                mma_f16(acc[2 * np + 1], a, bl + 2);
            }
        }

        int row0 = t * 64;
        int r0 = row0 + m0 + (lane >> 2);
        int r1 = r0 + 8;
        float s0 = (r0 < NN) ? d_dinv[r0] : 0.f;
        float s1 = (r1 < NN) ? d_dinv[r1] : 0.f;
        int c0 = wc * 64 + (lane & 3) * 2;
#pragma unroll
        for (int nt = 0; nt < 8; nt++) {
            int col = c0 + nt * 8;
            if (r0 < NN)
                *reinterpret_cast<__half2*>(&g_hb[(size_t)r0 * HH + col]) =
                    __floats2half2_rn(acc[nt][0] * s0, acc[nt][1] * s0);
            if (r1 < NN)
                *reinterpret_cast<__half2*>(&g_hb[(size_t)r1 * HH + col]) =
                    __floats2half2_rn(acc[nt][2] * s1, acc[nt][3] * s1);
        }
        __syncthreads();
    }
}

// ---------------------------------------------------------------- aggregation
__global__ void k_agg(const float* __restrict__ x, const float* __restrict__ bias,
                      float* __restrict__ outp, int relu, int to_out, int pre_scaled) {
    int gtid = blockIdx.x * blockDim.x + threadIdx.x;
    int node = gtid >> 5;
    int lane = gtid & 31;
    if (node >= NN) return;

    const uint2* g2 = reinterpret_cast<const uint2*>(g_hb);
    size_t base = (size_t)node * 32;
    float dv = d_dinv[node];

    uint2 sv = g2[base + lane];
    float2 f0 = __half22float2(*reinterpret_cast<__half2*>(&sv.x));
    float2 f1 = __half22float2(*reinterpret_cast<__half2*>(&sv.y));
    float selfs = pre_scaled ? 1.f : dv;
    float4 acc = make_float4(f0.x * selfs, f0.y * selfs, f1.x * selfs, f1.y * selfs);

    int e0 = d_rowstart[node];
    int e1 = d_rowstart[node + 1];
    int e = e0;
    if (pre_scaled) {
        for (; e + 8 <= e1; e += 8) {
            int si[8];
            uint2 vv[8];
#pragma unroll
            for (int q = 0; q < 8; q++) si[q] = d_srcs[e + q];
#pragma unroll
            for (int q = 0; q < 8; q++) vv[q] = g2[(size_t)si[q] * 32 + lane];
#pragma unroll
            for (int q = 0; q < 8; q++) {
                float2 a0 = __half22float2(*reinterpret_cast<__half2*>(&vv[q].x));
                float2 a1 = __half22float2(*reinterpret_cast<__half2*>(&vv[q].y));
                acc.x += a0.x; acc.y += a0.y; acc.z += a1.x; acc.w += a1.y;
            }
        }
        for (; e < e1; ++e) {
            uint2 v = g2[(size_t)d_srcs[e] * 32 + lane];
            float2 a0 = __half22float2(*reinterpret_cast<__half2*>(&v.x));
            float2 a1 = __half22float2(*reinterpret_cast<__half2*>(&v.y));
            acc.x += a0.x; acc.y += a0.y; acc.z += a1.x; acc.w += a1.y;
        }
    } else {
        for (; e + 8 <= e1; e += 8) {
            int si[8];
            uint2 vv[8];
            float dd[8];
#pragma unroll
            for (int q = 0; q < 8; q++) si[q] = d_srcs[e + q];
#pragma unroll
            for (int q = 0; q < 8; q++) vv[q] = g2[(size_t)si[q] * 32 + lane];
#pragma unroll
            for (int q = 0; q < 8; q++) dd[q] = d_dinv[si[q]];
#pragma unroll
            for (int q = 0; q < 8; q++) {
                float2 a0 = __half22float2(*reinterpret_cast<__half2*>(&vv[q].x));
                float2 a1 = __half22float2(*reinterpret_cast<__half2*>(&vv[q].y));
                acc.x = fmaf(dd[q], a0.x, acc.x);
                acc.y = fmaf(dd[q], a0.y, acc.y);
                acc.z = fmaf(dd[q], a1.x, acc.z);
                acc.w = fmaf(dd[q], a1.y, acc.w);
            }
        }
        for (; e < e1; ++e) {
            int s = d_srcs[e];
            float d = d_dinv[s];
            uint2 v = g2[(size_t)s * 32 + lane];
            float2 a0 = __half22float2(*reinterpret_cast<__half2*>(&v.x));
            float2 a1 = __half22float2(*reinterpret_cast<__half2*>(&v.y));
            acc.x = fmaf(d, a0.x, acc.x);
            acc.y = fmaf(d, a0.y, acc.y);
            acc.z = fmaf(d, a1.x, acc.z);
            acc.w = fmaf(d, a1.y, acc.w);
        }
    }
    size_t cbase = (size_t)node * HH + lane * 4;
    float4 bb = *reinterpret_cast<const float4*>(bias + lane * 4);
    float4 xv = *reinterpret_cast<const float4*>(x + cbase);
    float4 o;
    o.x = fmaf(dv, acc.x, bb.x + xv.x);
    o.y = fmaf(dv, acc.y, bb.y + xv.y);
    o.z = fmaf(dv, acc.z, bb.z + xv.z);
    o.w = fmaf(dv, acc.w, bb.w + xv.w);
    if (relu) {
        o.x = fmaxf(o.x, 0.f); o.y = fmaxf(o.y, 0.f);
        o.z = fmaxf(o.z, 0.f); o.w = fmaxf(o.w, 0.f);
    }
    if (to_out) {
        *reinterpret_cast<float4*>(outp + cbase) = o;
    } else {
        uint2 pk;
        *reinterpret_cast<__half2*>(&pk.x) = __floats2half2_rn(o.x, o.y);
        *reinterpret_cast<__half2*>(&pk.y) = __floats2half2_rn(o.z, o.w);
        *reinterpret_cast<uint2*>(&h_hb[cbase]) = pk;
    }
}

// ---------------------------------------------------------------- launch
extern "C" void kernel_launch(void* const* d_in, const int* in_sizes, int n_in,
                              void* d_out, int out_size) {
    const float* x   = (const float*)d_in[0];
    const int*   src = (const int*)  d_in[1];
    const int*   dst = (const int*)  d_in[2];
    const float* W1  = (const float*)d_in[3];
    const float* b1  = (const float*)d_in[4];
    const float* W2  = (const float*)d_in[5];
    const float* b2  = (const float*)d_in[6];
    float* out = (float*)d_out;

    (void)in_sizes; (void)n_in; (void)out_size;

    static int inited = 0;
    static cudaStream_t s1;
    static cudaEvent_t evFork, evJoin;
    if (!inited) {
        cudaFuncSetAttribute(k_gemm1,  cudaFuncAttributeMaxDynamicSharedMemorySize, SM1_TOTAL);
        cudaFuncSetAttribute(k_gemm23, cudaFuncAttributeMaxDynamicSharedMemorySize, SM2_TOTAL);
        cudaStreamCreateWithFlags(&s1, cudaStreamNonBlocking);
        cudaEventCreateWithFlags(&evFork, cudaEventDisableTiming);
        cudaEventCreateWithFlags(&evJoin, cudaEventDisableTiming);
        inited = 1;
    }

    __nv_bfloat16 *w1h, *w1l;
    __half *w2h, *w2l;
    cudaGetSymbolAddress((void**)&w1h, d_W1h);
    cudaGetSymbolAddress((void**)&w1l, d_W1l);
    cudaGetSymbolAddress((void**)&w2h, d_W2h);
    cudaGetSymbolAddress((void**)&w2l, d_W2l);

    const int gemm23_grid = 296;              // persistent: 2 CTAs x 148 SMs
    const int agg_grid  = (NN * 32 + 255) / 256;

    // Fork: CSR build + W2 prep on s1; W1 prep + GEMM1 on main stream.
    cudaEventRecord(evFork, 0);
    cudaStreamWaitEvent(s1, evFork, 0);

    k_zero_deg<<<(NN / 4 + 255) / 256, 256, 0, s1>>>();
    k_count   <<<(EE / 4 + 255) / 256, 256, 0, s1>>>(dst);
    k_scan    <<<1, 1024, 0, s1>>>();
    k_scatter <<<(EE / 4 + 255) / 256, 256, 0, s1>>>(src, dst);
    k_prepw_f16<<<64, 256, 0, s1>>>(W2, w2h, w2l);
    cudaEventRecord(evJoin, s1);

    k_prepw_bf16<<<64, 256>>>(W1, w1h, w1l);
    k_gemm1<<<NTILES, 256, SM1_TOTAL>>>(x, w1h, w1l);   // overlaps CSR

    cudaStreamWaitEvent(0, evJoin, 0);

    // layer 1 (g unscaled -> agg applies dinv[src])
    k_agg<<<agg_grid, 256>>>(x, b1, out, 1, 0, /*pre_scaled=*/0);
    // layer 2
    k_gemm23<<<gemm23_grid, 256, SM2_TOTAL>>>(w2h, w2l);
    k_agg<<<agg_grid, 256>>>(x, b2, out, 1, 0, /*pre_scaled=*/1);
    // layer 3
    k_gemm23<<<gemm23_grid, 256, SM2_TOTAL>>>(w2h, w2l);
    k_agg<<<agg_grid, 256>>>(x, b2, out, 0, 1, /*pre_scaled=*/1);
}

// round 15
// speedup vs baseline: 1.4030x; 1.0726x over previous
#include <cuda_runtime.h>
#include <cuda_bf16.h>
#include <cuda_fp16.h>
#include <cstdint>

#define NN 100000
#define EE 1600000
#define HH 128
#define NTILES ((NN + 63) / 64)      // 1563

typedef unsigned long long ull;

// ---- scratch (device globals) ----
static __device__ __half g_hb[(size_t)NN * HH];   // GEMM output, fp16
static __device__ __half h_hb[(size_t)NN * HH];   // layer activations (relu'd), fp16
static __device__ float  d_dinv[NN];
static __device__ int    d_deg[NN];
static __device__ int    d_rowstart[NN + 1];
static __device__ int    d_cursor[NN];
static __device__ int    d_srcs[EE];
#define LDA 136
static __device__ __nv_bfloat16 d_W1h[128 * LDA], d_W1l[128 * LDA];
static __device__ __half d_W2h[128 * LDA], d_W2l[128 * LDA];

// ---------------------------------------------------------------- CSR build
__global__ void k_zero_deg() {
    int i = blockIdx.x * blockDim.x + threadIdx.x;
    if (i < NN / 4) reinterpret_cast<int4*>(d_deg)[i] = make_int4(0, 0, 0, 0);
}

__global__ void k_count(const int* __restrict__ dst) {
    int i = blockIdx.x * blockDim.x + threadIdx.x;
    if (i >= EE / 4) return;
    int4 d = reinterpret_cast<const int4*>(dst)[i];
    atomicAdd(&d_deg[d.x], 1);
    atomicAdd(&d_deg[d.y], 1);
    atomicAdd(&d_deg[d.z], 1);
    atomicAdd(&d_deg[d.w], 1);
}

__global__ void k_scan() {
    __shared__ int warpsum[32];
    int tid  = threadIdx.x;
    int lane = tid & 31;
    int wid  = tid >> 5;
    int running = 0;
    for (int base = 0; base < NN; base += 4096) {
        int gi = base + tid * 4;
        int4 v = make_int4(0, 0, 0, 0);
        if (gi + 3 < NN) {
            v = *reinterpret_cast<const int4*>(&d_deg[gi]);
        } else {
            if (gi     < NN) v.x = d_deg[gi];
            if (gi + 1 < NN) v.y = d_deg[gi + 1];
            if (gi + 2 < NN) v.z = d_deg[gi + 2];
            if (gi + 3 < NN) v.w = d_deg[gi + 3];
        }
        int t = v.x + v.y + v.z + v.w;
        int inc = t;
#pragma unroll
        for (int off = 1; off < 32; off <<= 1) {
            int n = __shfl_up_sync(0xffffffffu, inc, off);
            if (lane >= off) inc += n;
        }
        if (lane == 31) warpsum[wid] = inc;
        __syncthreads();
        if (wid == 0) {
            int wi = warpsum[lane];
#pragma unroll
            for (int off = 1; off < 32; off <<= 1) {
                int n = __shfl_up_sync(0xffffffffu, wi, off);
                if (lane >= off) wi += n;
            }
            warpsum[lane] = wi;
        }
        __syncthreads();
        int warpoff = (wid > 0) ? warpsum[wid - 1] : 0;
        int excl = running + warpoff + inc - t;
        if (gi < NN) {
            d_rowstart[gi] = excl; d_cursor[gi] = excl;
            d_dinv[gi] = rsqrtf((float)(v.x + 1)); excl += v.x;
        }
        if (gi + 1 < NN) {
            d_rowstart[gi + 1] = excl; d_cursor[gi + 1] = excl;
            d_dinv[gi + 1] = rsqrtf((float)(v.y + 1)); excl += v.y;
        }
        if (gi + 2 < NN) {
            d_rowstart[gi + 2] = excl; d_cursor[gi + 2] = excl;
            d_dinv[gi + 2] = rsqrtf((float)(v.z + 1)); excl += v.z;
        }
        if (gi + 3 < NN) {
            d_rowstart[gi + 3] = excl; d_cursor[gi + 3] = excl;
            d_dinv[gi + 3] = rsqrtf((float)(v.w + 1));
        }
        int tot = warpsum[31];
        __syncthreads();
        running += tot;
    }
    if (tid == 0) d_rowstart[NN] = EE;
}

__global__ void k_scatter(const int* __restrict__ src, const int* __restrict__ dst) {
    int i = blockIdx.x * blockDim.x + threadIdx.x;
    if (i >= EE / 4) return;
    int4 d = reinterpret_cast<const int4*>(dst)[i];
    int4 s = reinterpret_cast<const int4*>(src)[i];
    d_srcs[atomicAdd(&d_cursor[d.x], 1)] = s.x;
    d_srcs[atomicAdd(&d_cursor[d.y], 1)] = s.y;
    d_srcs[atomicAdd(&d_cursor[d.z], 1)] = s.z;
    d_srcs[atomicAdd(&d_cursor[d.w], 1)] = s.w;
}

// ---------------------------------------------------------------- W pre-convert
__global__ void k_prepw_bf16(const float* __restrict__ W,
                             __nv_bfloat16* __restrict__ oh, __nv_bfloat16* __restrict__ ol) {
    int idx = blockIdx.x * blockDim.x + threadIdx.x;
    if (idx >= 128 * 128) return;
    int k = idx >> 7;
    int n = idx & 127;
    float v = W[(size_t)k * HH + n];
    __nv_bfloat16 h = __float2bfloat16_rn(v);
    __nv_bfloat16 l = __float2bfloat16_rn(v - __bfloat162float(h));
    oh[n * LDA + k] = h;
    ol[n * LDA + k] = l;
}

__global__ void k_prepw_f16(const float* __restrict__ W,
                            __half* __restrict__ oh, __half* __restrict__ ol) {
    int idx = blockIdx.x * blockDim.x + threadIdx.x;
    if (idx >= 128 * 128) return;
    int k = idx >> 7;
    int n = idx & 127;
    float v = W[(size_t)k * HH + n];
    __half h = __float2half_rn(v);
    __half l = __float2half_rn(v - __half2float(h));
    oh[n * LDA + k] = h;
    ol[n * LDA + k] = l;
}

// ---------------------------------------------------------------- mma utils
__device__ __forceinline__ uint32_t smem_u32(const void* p) {
    uint32_t a;
    asm("{ .reg .u64 t; cvta.to.shared.u64 t, %1; cvt.u32.u64 %0, t; }" : "=r"(a) : "l"(p));
    return a;
}
__device__ __forceinline__ void ldsm4(uint32_t* r, uint32_t addr) {
    asm volatile("ldmatrix.sync.aligned.m8n8.x4.shared.b16 {%0,%1,%2,%3}, [%4];"
                 : "=r"(r[0]), "=r"(r[1]), "=r"(r[2]), "=r"(r[3]) : "r"(addr));
}
__device__ __forceinline__ void mma_bf16(float* d, const uint32_t* a, const uint32_t* b) {
    asm volatile(
        "mma.sync.aligned.m16n8k16.row.col.f32.bf16.bf16.f32 "
        "{%0,%1,%2,%3}, {%4,%5,%6,%7}, {%8,%9}, {%0,%1,%2,%3};"
        : "+f"(d[0]), "+f"(d[1]), "+f"(d[2]), "+f"(d[3])
        : "r"(a[0]), "r"(a[1]), "r"(a[2]), "r"(a[3]), "r"(b[0]), "r"(b[1]));
}
__device__ __forceinline__ void mma_f16(float* d, const uint32_t* a, const uint32_t* b) {
    asm volatile(
        "mma.sync.aligned.m16n8k16.row.col.f32.f16.f16.f32 "
        "{%0,%1,%2,%3}, {%4,%5,%6,%7}, {%8,%9}, {%0,%1,%2,%3};"
        : "+f"(d[0]), "+f"(d[1]), "+f"(d[2]), "+f"(d[3])
        : "r"(a[0]), "r"(a[1]), "r"(a[2]), "r"(a[3]), "r"(b[0]), "r"(b[1]));
}
__device__ __forceinline__ uint32_t pack_hi(float x, float y, uint32_t& lo) {
    __nv_bfloat16 h0 = __float2bfloat16_rn(x);
    __nv_bfloat16 h1 = __float2bfloat16_rn(y);
    __nv_bfloat16 l0 = __float2bfloat16_rn(x - __bfloat162float(h0));
    __nv_bfloat16 l1 = __float2bfloat16_rn(y - __bfloat162float(h1));
    lo = (uint32_t)__bfloat16_as_ushort(l0) | ((uint32_t)__bfloat16_as_ushort(l1) << 16);
    return (uint32_t)__bfloat16_as_ushort(h0) | ((uint32_t)__bfloat16_as_ushort(h1) << 16);
}

#define A_TILE_B (64 * LDA * 2)
#define B_TILE_B (128 * LDA * 2)

// ---------------------------------------------------------------- GEMM layer 1
#define SM1_AH 0
#define SM1_AL (A_TILE_B)
#define SM1_BH (2 * A_TILE_B)
#define SM1_BL (2 * A_TILE_B + B_TILE_B)
#define SM1_TOTAL (2 * A_TILE_B + 2 * B_TILE_B)

__global__ void __launch_bounds__(256, 2)
k_gemm1(const float* __restrict__ xf32,
        const __nv_bfloat16* __restrict__ Wh, const __nv_bfloat16* __restrict__ Wl) {
    extern __shared__ __align__(16) char smem[];
    uint32_t sb = smem_u32(smem);
    int tid  = threadIdx.x;
    int wid  = tid >> 5;
    int lane = tid & 31;
    int row0 = blockIdx.x * 64;

    for (int idx = tid; idx < 64 * 64; idx += 256) {
        int r  = idx >> 6;
        int kp = idx & 63;
        int grow = row0 + r;
        float2 v = make_float2(0.f, 0.f);
        if (grow < NN)
            v = *reinterpret_cast<const float2*>(xf32 + (size_t)grow * HH + kp * 2);
        uint32_t lo, hi = pack_hi(v.x, v.y, lo);
        uint32_t off = (uint32_t)(r * LDA + kp * 2) * 2;
        *reinterpret_cast<uint32_t*>(smem + SM1_AH + off) = hi;
        *reinterpret_cast<uint32_t*>(smem + SM1_AL + off) = lo;
    }
    {
        const uint4* gh = reinterpret_cast<const uint4*>(Wh);
        const uint4* gl = reinterpret_cast<const uint4*>(Wl);
        uint4* shv = reinterpret_cast<uint4*>(smem + SM1_BH);
        uint4* slv = reinterpret_cast<uint4*>(smem + SM1_BL);
        for (int i = tid; i < B_TILE_B / 16; i += 256) {
            shv[i] = gh[i];
            slv[i] = gl[i];
        }
    }
    __syncthreads();

    int wr = wid & 3;
    int wc = wid >> 2;
    int m0 = wr * 16;
    float acc[8][4];
#pragma unroll
    for (int i = 0; i < 8; i++)
#pragma unroll
        for (int j = 0; j < 4; j++) acc[i][j] = 0.f;

    uint32_t a_off = (uint32_t)((m0 + (lane & 15)) * LDA + ((lane >> 4) << 3)) * 2;
    uint32_t b_off = (uint32_t)(((lane & 7) + ((lane >> 1) & 8)) * LDA + (lane & 8)) * 2;

#pragma unroll
    for (int ks = 0; ks < 8; ks++) {
        int k0 = ks * 16;
        uint32_t ah[4], al[4];
        ldsm4(ah, sb + SM1_AH + a_off + k0 * 2);
        ldsm4(al, sb + SM1_AL + a_off + k0 * 2);
#pragma unroll
        for (int np = 0; np < 4; np++) {
            uint32_t bh[4], bl[4];
            uint32_t bo = (uint32_t)((wc * 64 + np * 16) * LDA + k0) * 2 + b_off;
            ldsm4(bh, sb + SM1_BH + bo);
            ldsm4(bl, sb + SM1_BL + bo);
            mma_bf16(acc[2 * np],     ah, bh);
            mma_bf16(acc[2 * np + 1], ah, bh + 2);
            mma_bf16(acc[2 * np],     al, bh);
            mma_bf16(acc[2 * np + 1], al, bh + 2);
            mma_bf16(acc[2 * np],     ah, bl);
            mma_bf16(acc[2 * np + 1], ah, bl + 2);
        }
    }

    int r0 = row0 + m0 + (lane >> 2);
    int r1 = r0 + 8;
    int c0 = wc * 64 + (lane & 3) * 2;
#pragma unroll
    for (int nt = 0; nt < 8; nt++) {
        int col = c0 + nt * 8;
        if (r0 < NN)
            *reinterpret_cast<__half2*>(&g_hb[(size_t)r0 * HH + col]) =
                __floats2half2_rn(acc[nt][0], acc[nt][1]);
        if (r1 < NN)
            *reinterpret_cast<__half2*>(&g_hb[(size_t)r1 * HH + col]) =
                __floats2half2_rn(acc[nt][2], acc[nt][3]);
    }
}

// ---------------------------------------------------------------- GEMM 2/3
// Persistent; f16; A double-buffered; B staged once; dinv in epilogue.
// two_term=1: D = A@Wh + A@Wl (layer 2). two_term=0: D = A@Wh only (layer 3).
#define SM2_A0 0
#define SM2_A1 (A_TILE_B)
#define SM2_BH (2 * A_TILE_B)
#define SM2_BL (2 * A_TILE_B + B_TILE_B)
#define SM2_TOTAL (2 * A_TILE_B + 2 * B_TILE_B)

__global__ void __launch_bounds__(256, 2)
k_gemm23(const __half* __restrict__ Wh, const __half* __restrict__ Wl, int two_term) {
    extern __shared__ __align__(16) char smem[];
    uint32_t sb = smem_u32(smem);
    int tid  = threadIdx.x;
    int wid  = tid >> 5;
    int lane = tid & 31;

    {
        const uint4* gh = reinterpret_cast<const uint4*>(Wh);
        uint4* shv = reinterpret_cast<uint4*>(smem + SM2_BH);
        for (int i = tid; i < B_TILE_B / 16; i += 256) shv[i] = gh[i];
        if (two_term) {
            const uint4* gl = reinterpret_cast<const uint4*>(Wl);
            uint4* slv = reinterpret_cast<uint4*>(smem + SM2_BL);
            for (int i = tid; i < B_TILE_B / 16; i += 256) slv[i] = gl[i];
        }
    }

    auto stageA = [&](int tile, int bufsel) {
        int row0 = tile * 64;
        char* dstb = smem + (bufsel ? SM2_A1 : SM2_A0);
        const __half* A16 = (const __half*)h_hb;
        for (int idx = tid; idx < 64 * 32; idx += 256) {
            int r  = idx >> 5;
            int k4 = (idx & 31) * 4;
            int grow = row0 + r;
            uint2 v = make_uint2(0u, 0u);
            if (grow < NN)
                v = *reinterpret_cast<const uint2*>(A16 + (size_t)grow * HH + k4);
            *reinterpret_cast<uint2*>(dstb + (uint32_t)(r * LDA + k4) * 2) = v;
        }
    };

    int wr = wid & 3;
    int wc = wid >> 2;
    int m0 = wr * 16;
    uint32_t a_off = (uint32_t)((m0 + (lane & 15)) * LDA + ((lane >> 4) << 3)) * 2;
    uint32_t b_off = (uint32_t)(((lane & 7) + ((lane >> 1) & 8)) * LDA + (lane & 8)) * 2;

    int t0 = blockIdx.x;
    if (t0 < NTILES) stageA(t0, 0);
    __syncthreads();

    int buf = 0;
    for (int t = t0; t < NTILES; t += gridDim.x, buf ^= 1) {
        int nxt = t + gridDim.x;
        if (nxt < NTILES) stageA(nxt, buf ^ 1);

        uint32_t abase = sb + (buf ? SM2_A1 : SM2_A0) + a_off;
        float acc[8][4];
#pragma unroll
        for (int i = 0; i < 8; i++)
#pragma unroll
            for (int j = 0; j < 4; j++) acc[i][j] = 0.f;

#pragma unroll
        for (int ks = 0; ks < 8; ks++) {
            int k0 = ks * 16;
            uint32_t a[4];
            ldsm4(a, abase + k0 * 2);
#pragma unroll
            for (int np = 0; np < 4; np++) {
                uint32_t bh[4];
                uint32_t bo = (uint32_t)((wc * 64 + np * 16) * LDA + k0) * 2 + b_off;
                ldsm4(bh, sb + SM2_BH + bo);
                mma_f16(acc[2 * np],     a, bh);
                mma_f16(acc[2 * np + 1], a, bh + 2);
                if (two_term) {
                    uint32_t bl[4];
                    ldsm4(bl, sb + SM2_BL + bo);
                    mma_f16(acc[2 * np],     a, bl);
                    mma_f16(acc[2 * np + 1], a, bl + 2);
                }
            }
        }

        int row0 = t * 64;
        int r0 = row0 + m0 + (lane >> 2);
        int r1 = r0 + 8;
        float s0 = (r0 < NN) ? d_dinv[r0] : 0.f;
        float s1 = (r1 < NN) ? d_dinv[r1] : 0.f;
        int c0 = wc * 64 + (lane & 3) * 2;
#pragma unroll
        for (int nt = 0; nt < 8; nt++) {
            int col = c0 + nt * 8;
            if (r0 < NN)
                *reinterpret_cast<__half2*>(&g_hb[(size_t)r0 * HH + col]) =
                    __floats2half2_rn(acc[nt][0] * s0, acc[nt][1] * s0);
            if (r1 < NN)
                *reinterpret_cast<__half2*>(&g_hb[(size_t)r1 * HH + col]) =
                    __floats2half2_rn(acc[nt][2] * s1, acc[nt][3] * s1);
        }
        __syncthreads();
    }
}

// ---------------------------------------------------------------- aggregation (R9 unroll-4)
__global__ void k_agg(const float* __restrict__ x, const float* __restrict__ bias,
                      float* __restrict__ outp, int relu, int to_out, int pre_scaled) {
    int gtid = blockIdx.x * blockDim.x + threadIdx.x;
    int node = gtid >> 5;
    int lane = gtid & 31;
    if (node >= NN) return;

    const uint2* g2 = reinterpret_cast<const uint2*>(g_hb);
    size_t base = (size_t)node * 32;
    float dv = d_dinv[node];

    uint2 sv = g2[base + lane];
    float2 f0 = __half22float2(*reinterpret_cast<__half2*>(&sv.x));
    float2 f1 = __half22float2(*reinterpret_cast<__half2*>(&sv.y));
    float selfs = pre_scaled ? 1.f : dv;
    float4 acc = make_float4(f0.x * selfs, f0.y * selfs, f1.x * selfs, f1.y * selfs);

    int e0 = d_rowstart[node];
    int e1 = d_rowstart[node + 1];
    int e = e0;
    if (pre_scaled) {
        for (; e + 4 <= e1; e += 4) {
            int s0 = d_srcs[e], s1 = d_srcs[e + 1], s2 = d_srcs[e + 2], s3 = d_srcs[e + 3];
            uint2 v0 = g2[(size_t)s0 * 32 + lane];
            uint2 v1 = g2[(size_t)s1 * 32 + lane];
            uint2 v2 = g2[(size_t)s2 * 32 + lane];
            uint2 v3 = g2[(size_t)s3 * 32 + lane];
#define ACC4(v) { \
            float2 a0 = __half22float2(*reinterpret_cast<__half2*>(&(v).x)); \
            float2 a1 = __half22float2(*reinterpret_cast<__half2*>(&(v).y)); \
            acc.x += a0.x; acc.y += a0.y; acc.z += a1.x; acc.w += a1.y; }
            ACC4(v0) ACC4(v1) ACC4(v2) ACC4(v3)
        }
        for (; e < e1; ++e) {
            uint2 v = g2[(size_t)d_srcs[e] * 32 + lane];
            ACC4(v)
        }
#undef ACC4
    } else {
        for (; e + 4 <= e1; e += 4) {
            int s0 = d_srcs[e], s1 = d_srcs[e + 1], s2 = d_srcs[e + 2], s3 = d_srcs[e + 3];
            float d0 = d_dinv[s0], d1 = d_dinv[s1], d2 = d_dinv[s2], d3 = d_dinv[s3];
            uint2 v0 = g2[(size_t)s0 * 32 + lane];
            uint2 v1 = g2[(size_t)s1 * 32 + lane];
            uint2 v2 = g2[(size_t)s2 * 32 + lane];
            uint2 v3 = g2[(size_t)s3 * 32 + lane];
#define ACCD(v, d) { \
            float2 a0 = __half22float2(*reinterpret_cast<__half2*>(&(v).x)); \
            float2 a1 = __half22float2(*reinterpret_cast<__half2*>(&(v).y)); \
            acc.x = fmaf((d), a0.x, acc.x); acc.y = fmaf((d), a0.y, acc.y); \
            acc.z = fmaf((d), a1.x, acc.z); acc.w = fmaf((d), a1.y, acc.w); }
            ACCD(v0, d0) ACCD(v1, d1) ACCD(v2, d2) ACCD(v3, d3)
        }
        for (; e < e1; ++e) {
            int s = d_srcs[e];
            float d = d_dinv[s];
            uint2 v = g2[(size_t)s * 32 + lane];
            ACCD(v, d)
        }
#undef ACCD
    }
    size_t cbase = (size_t)node * HH + lane * 4;
    float4 bb = *reinterpret_cast<const float4*>(bias + lane * 4);
    float4 xv = *reinterpret_cast<const float4*>(x + cbase);
    float4 o;
    o.x = fmaf(dv, acc.x, bb.x + xv.x);
    o.y = fmaf(dv, acc.y, bb.y + xv.y);
    o.z = fmaf(dv, acc.z, bb.z + xv.z);
    o.w = fmaf(dv, acc.w, bb.w + xv.w);
    if (relu) {
        o.x = fmaxf(o.x, 0.f); o.y = fmaxf(o.y, 0.f);
        o.z = fmaxf(o.z, 0.f); o.w = fmaxf(o.w, 0.f);
    }
    if (to_out) {
        *reinterpret_cast<float4*>(outp + cbase) = o;
    } else {
        uint2 pk;
        *reinterpret_cast<__half2*>(&pk.x) = __floats2half2_rn(o.x, o.y);
        *reinterpret_cast<__half2*>(&pk.y) = __floats2half2_rn(o.z, o.w);
        *reinterpret_cast<uint2*>(&h_hb[cbase]) = pk;
    }
}

// ---------------------------------------------------------------- launch
extern "C" void kernel_launch(void* const* d_in, const int* in_sizes, int n_in,
                              void* d_out, int out_size) {
    const float* x   = (const float*)d_in[0];
    const int*   src = (const int*)  d_in[1];
    const int*   dst = (const int*)  d_in[2];
    const float* W1  = (const float*)d_in[3];
    const float* b1  = (const float*)d_in[4];
    const float* W2  = (const float*)d_in[5];
    const float* b2  = (const float*)d_in[6];
    float* out = (float*)d_out;

    (void)in_sizes; (void)n_in; (void)out_size;

    static int inited = 0;
    static cudaStream_t s1;
    static cudaEvent_t evFork, evJoin;
    if (!inited) {
        cudaFuncSetAttribute(k_gemm1,  cudaFuncAttributeMaxDynamicSharedMemorySize, SM1_TOTAL);
        cudaFuncSetAttribute(k_gemm23, cudaFuncAttributeMaxDynamicSharedMemorySize, SM2_TOTAL);
        cudaStreamCreateWithFlags(&s1, cudaStreamNonBlocking);
        cudaEventCreateWithFlags(&evFork, cudaEventDisableTiming);
        cudaEventCreateWithFlags(&evJoin, cudaEventDisableTiming);
        inited = 1;
    }

    __nv_bfloat16 *w1h, *w1l;
    __half *w2h, *w2l;
    cudaGetSymbolAddress((void**)&w1h, d_W1h);
    cudaGetSymbolAddress((void**)&w1l, d_W1l);
    cudaGetSymbolAddress((void**)&w2h, d_W2h);
    cudaGetSymbolAddress((void**)&w2l, d_W2l);

    const int gemm23_grid = 296;              // persistent: 2 CTAs x 148 SMs
    const int agg_grid  = (NN * 32 + 255) / 256;

    // Fork: CSR build + W2 prep on s1; W1 prep + GEMM1 on main stream.
    cudaEventRecord(evFork, 0);
    cudaStreamWaitEvent(s1, evFork, 0);

    k_zero_deg<<<(NN / 4 + 255) / 256, 256, 0, s1>>>();
    k_count   <<<(EE / 4 + 255) / 256, 256, 0, s1>>>(dst);
    k_scan    <<<1, 1024, 0, s1>>>();
    k_scatter <<<(EE / 4 + 255) / 256, 256, 0, s1>>>(src, dst);
    k_prepw_f16<<<64, 256, 0, s1>>>(W2, w2h, w2l);
    cudaEventRecord(evJoin, s1);

    k_prepw_bf16<<<64, 256>>>(W1, w1h, w1l);
    k_gemm1<<<NTILES, 256, SM1_TOTAL>>>(x, w1h, w1l);   // overlaps CSR

    cudaStreamWaitEvent(0, evJoin, 0);

    // layer 1 (g unscaled -> agg applies dinv[src])
    k_agg<<<agg_grid, 256>>>(x, b1, out, 1, 0, /*pre_scaled=*/0);
    // layer 2 (full 2-term)
    k_gemm23<<<gemm23_grid, 256, SM2_TOTAL>>>(w2h, w2l, /*two_term=*/1);
    k_agg<<<agg_grid, 256>>>(x, b2, out, 1, 0, /*pre_scaled=*/1);
    // layer 3 (1-term: last layer, error does not propagate)
    k_gemm23<<<gemm23_grid, 256, SM2_TOTAL>>>(w2h, w2l, /*two_term=*/0);
    k_agg<<<agg_grid, 256>>>(x, b2, out, 0, 1, /*pre_scaled=*/1);
}

// round 16
// speedup vs baseline: 1.4076x; 1.0032x over previous
#include <cuda_runtime.h>
#include <cuda_bf16.h>
#include <cuda_fp16.h>
#include <cstdint>

#define NN 100000
#define EE 1600000
#define HH 128
#define NTILES ((NN + 63) / 64)      // 1563

typedef unsigned long long ull;

// ---- scratch (device globals) ----
static __device__ __half g_hb[(size_t)NN * HH];   // GEMM output, fp16
static __device__ __half h_hb[(size_t)NN * HH];   // layer activations (relu'd), fp16
static __device__ float  d_dinv[NN];
static __device__ int    d_deg[NN];
static __device__ int    d_rowstart[NN + 1];
static __device__ int    d_cursor[NN];
static __device__ int    d_srcs[EE];
#define LDA 136
static __device__ __nv_bfloat16 d_W1h[128 * LDA], d_W1l[128 * LDA];
static __device__ __half d_W2h[128 * LDA], d_W2l[128 * LDA];

// ---------------------------------------------------------------- CSR build
__global__ void k_zero_deg() {
    int i = blockIdx.x * blockDim.x + threadIdx.x;
    if (i < NN / 4) reinterpret_cast<int4*>(d_deg)[i] = make_int4(0, 0, 0, 0);
}

__global__ void k_count(const int* __restrict__ dst) {
    int i = blockIdx.x * blockDim.x + threadIdx.x;
    if (i >= EE / 4) return;
    int4 d = reinterpret_cast<const int4*>(dst)[i];
    atomicAdd(&d_deg[d.x], 1);
    atomicAdd(&d_deg[d.y], 1);
    atomicAdd(&d_deg[d.z], 1);
    atomicAdd(&d_deg[d.w], 1);
}

__global__ void k_scan() {
    __shared__ int warpsum[32];
    int tid  = threadIdx.x;
    int lane = tid & 31;
    int wid  = tid >> 5;
    int running = 0;
    for (int base = 0; base < NN; base += 4096) {
        int gi = base + tid * 4;
        int4 v = make_int4(0, 0, 0, 0);
        if (gi + 3 < NN) {
            v = *reinterpret_cast<const int4*>(&d_deg[gi]);
        } else {
            if (gi     < NN) v.x = d_deg[gi];
            if (gi + 1 < NN) v.y = d_deg[gi + 1];
            if (gi + 2 < NN) v.z = d_deg[gi + 2];
            if (gi + 3 < NN) v.w = d_deg[gi + 3];
        }
        int t = v.x + v.y + v.z + v.w;
        int inc = t;
#pragma unroll
        for (int off = 1; off < 32; off <<= 1) {
            int n = __shfl_up_sync(0xffffffffu, inc, off);
            if (lane >= off) inc += n;
        }
        if (lane == 31) warpsum[wid] = inc;
        __syncthreads();
        if (wid == 0) {
            int wi = warpsum[lane];
#pragma unroll
            for (int off = 1; off < 32; off <<= 1) {
                int n = __shfl_up_sync(0xffffffffu, wi, off);
                if (lane >= off) wi += n;
            }
            warpsum[lane] = wi;
        }
        __syncthreads();
        int warpoff = (wid > 0) ? warpsum[wid - 1] : 0;
        int excl = running + warpoff + inc - t;
        if (gi < NN) {
            d_rowstart[gi] = excl; d_cursor[gi] = excl;
            d_dinv[gi] = rsqrtf((float)(v.x + 1)); excl += v.x;
        }
        if (gi + 1 < NN) {
            d_rowstart[gi + 1] = excl; d_cursor[gi + 1] = excl;
            d_dinv[gi + 1] = rsqrtf((float)(v.y + 1)); excl += v.y;
        }
        if (gi + 2 < NN) {
            d_rowstart[gi + 2] = excl; d_cursor[gi + 2] = excl;
            d_dinv[gi + 2] = rsqrtf((float)(v.z + 1)); excl += v.z;
        }
        if (gi + 3 < NN) {
            d_rowstart[gi + 3] = excl; d_cursor[gi + 3] = excl;
            d_dinv[gi + 3] = rsqrtf((float)(v.w + 1));
        }
        int tot = warpsum[31];
        __syncthreads();
        running += tot;
    }
    if (tid == 0) d_rowstart[NN] = EE;
}

__global__ void k_scatter(const int* __restrict__ src, const int* __restrict__ dst) {
    int i = blockIdx.x * blockDim.x + threadIdx.x;
    if (i >= EE / 4) return;
    int4 d = reinterpret_cast<const int4*>(dst)[i];
    int4 s = reinterpret_cast<const int4*>(src)[i];
    d_srcs[atomicAdd(&d_cursor[d.x], 1)] = s.x;
    d_srcs[atomicAdd(&d_cursor[d.y], 1)] = s.y;
    d_srcs[atomicAdd(&d_cursor[d.z], 1)] = s.z;
    d_srcs[atomicAdd(&d_cursor[d.w], 1)] = s.w;
}

// ---------------------------------------------------------------- W pre-convert
__global__ void k_prepw_bf16(const float* __restrict__ W,
                             __nv_bfloat16* __restrict__ oh, __nv_bfloat16* __restrict__ ol) {
    int idx = blockIdx.x * blockDim.x + threadIdx.x;
    if (idx >= 128 * 128) return;
    int k = idx >> 7;
    int n = idx & 127;
    float v = W[(size_t)k * HH + n];
    __nv_bfloat16 h = __float2bfloat16_rn(v);
    __nv_bfloat16 l = __float2bfloat16_rn(v - __bfloat162float(h));
    oh[n * LDA + k] = h;
    ol[n * LDA + k] = l;
}

__global__ void k_prepw_f16(const float* __restrict__ W,
                            __half* __restrict__ oh, __half* __restrict__ ol) {
    int idx = blockIdx.x * blockDim.x + threadIdx.x;
    if (idx >= 128 * 128) return;
    int k = idx >> 7;
    int n = idx & 127;
    float v = W[(size_t)k * HH + n];
    __half h = __float2half_rn(v);
    __half l = __float2half_rn(v - __half2float(h));
    oh[n * LDA + k] = h;
    ol[n * LDA + k] = l;
}

// ---------------------------------------------------------------- mma utils
__device__ __forceinline__ uint32_t smem_u32(const void* p) {
    uint32_t a;
    asm("{ .reg .u64 t; cvta.to.shared.u64 t, %1; cvt.u32.u64 %0, t; }" : "=r"(a) : "l"(p));
    return a;
}
__device__ __forceinline__ void ldsm4(uint32_t* r, uint32_t addr) {
    asm volatile("ldmatrix.sync.aligned.m8n8.x4.shared.b16 {%0,%1,%2,%3}, [%4];"
                 : "=r"(r[0]), "=r"(r[1]), "=r"(r[2]), "=r"(r[3]) : "r"(addr));
}
__device__ __forceinline__ void mma_bf16(float* d, const uint32_t* a, const uint32_t* b) {
    asm volatile(
        "mma.sync.aligned.m16n8k16.row.col.f32.bf16.bf16.f32 "
        "{%0,%1,%2,%3}, {%4,%5,%6,%7}, {%8,%9}, {%0,%1,%2,%3};"
        : "+f"(d[0]), "+f"(d[1]), "+f"(d[2]), "+f"(d[3])
        : "r"(a[0]), "r"(a[1]), "r"(a[2]), "r"(a[3]), "r"(b[0]), "r"(b[1]));
}
__device__ __forceinline__ void mma_f16(float* d, const uint32_t* a, const uint32_t* b) {
    asm volatile(
        "mma.sync.aligned.m16n8k16.row.col.f32.f16.f16.f32 "
        "{%0,%1,%2,%3}, {%4,%5,%6,%7}, {%8,%9}, {%0,%1,%2,%3};"
        : "+f"(d[0]), "+f"(d[1]), "+f"(d[2]), "+f"(d[3])
        : "r"(a[0]), "r"(a[1]), "r"(a[2]), "r"(a[3]), "r"(b[0]), "r"(b[1]));
}
__device__ __forceinline__ uint32_t pack_hi(float x, float y, uint32_t& lo) {
    __nv_bfloat16 h0 = __float2bfloat16_rn(x);
    __nv_bfloat16 h1 = __float2bfloat16_rn(y);
    __nv_bfloat16 l0 = __float2bfloat16_rn(x - __bfloat162float(h0));
    __nv_bfloat16 l1 = __float2bfloat16_rn(y - __bfloat162float(h1));
    lo = (uint32_t)__bfloat16_as_ushort(l0) | ((uint32_t)__bfloat16_as_ushort(l1) << 16);
    return (uint32_t)__bfloat16_as_ushort(h0) | ((uint32_t)__bfloat16_as_ushort(h1) << 16);
}

#define A_TILE_B (64 * LDA * 2)
#define B_TILE_B (128 * LDA * 2)

// ---------------------------------------------------------------- GEMM layer 1
#define SM1_AH 0
#define SM1_AL (A_TILE_B)
#define SM1_BH (2 * A_TILE_B)
#define SM1_BL (2 * A_TILE_B + B_TILE_B)
#define SM1_TOTAL (2 * A_TILE_B + 2 * B_TILE_B)

__global__ void __launch_bounds__(256, 2)
k_gemm1(const float* __restrict__ xf32,
        const __nv_bfloat16* __restrict__ Wh, const __nv_bfloat16* __restrict__ Wl) {
    extern __shared__ __align__(16) char smem[];
    uint32_t sb = smem_u32(smem);
    int tid  = threadIdx.x;
    int wid  = tid >> 5;
    int lane = tid & 31;
    int row0 = blockIdx.x * 64;

    for (int idx = tid; idx < 64 * 64; idx += 256) {
        int r  = idx >> 6;
        int kp = idx & 63;
        int grow = row0 + r;
        float2 v = make_float2(0.f, 0.f);
        if (grow < NN)
            v = *reinterpret_cast<const float2*>(xf32 + (size_t)grow * HH + kp * 2);
        uint32_t lo, hi = pack_hi(v.x, v.y, lo);
        uint32_t off = (uint32_t)(r * LDA + kp * 2) * 2;
        *reinterpret_cast<uint32_t*>(smem + SM1_AH + off) = hi;
        *reinterpret_cast<uint32_t*>(smem + SM1_AL + off) = lo;
    }
    {
        const uint4* gh = reinterpret_cast<const uint4*>(Wh);
        const uint4* gl = reinterpret_cast<const uint4*>(Wl);
        uint4* shv = reinterpret_cast<uint4*>(smem + SM1_BH);
        uint4* slv = reinterpret_cast<uint4*>(smem + SM1_BL);
        for (int i = tid; i < B_TILE_B / 16; i += 256) {
            shv[i] = gh[i];
            slv[i] = gl[i];
        }
    }
    __syncthreads();

    int wr = wid & 3;
    int wc = wid >> 2;
    int m0 = wr * 16;
    float acc[8][4];
#pragma unroll
    for (int i = 0; i < 8; i++)
#pragma unroll
        for (int j = 0; j < 4; j++) acc[i][j] = 0.f;

    uint32_t a_off = (uint32_t)((m0 + (lane & 15)) * LDA + ((lane >> 4) << 3)) * 2;
    uint32_t b_off = (uint32_t)(((lane & 7) + ((lane >> 1) & 8)) * LDA + (lane & 8)) * 2;

#pragma unroll
    for (int ks = 0; ks < 8; ks++) {
        int k0 = ks * 16;
        uint32_t ah[4], al[4];
        ldsm4(ah, sb + SM1_AH + a_off + k0 * 2);
        ldsm4(al, sb + SM1_AL + a_off + k0 * 2);
#pragma unroll
        for (int np = 0; np < 4; np++) {
            uint32_t bh[4], bl[4];
            uint32_t bo = (uint32_t)((wc * 64 + np * 16) * LDA + k0) * 2 + b_off;
            ldsm4(bh, sb + SM1_BH + bo);
            ldsm4(bl, sb + SM1_BL + bo);
            mma_bf16(acc[2 * np],     ah, bh);
            mma_bf16(acc[2 * np + 1], ah, bh + 2);
            mma_bf16(acc[2 * np],     al, bh);
            mma_bf16(acc[2 * np + 1], al, bh + 2);
            mma_bf16(acc[2 * np],     ah, bl);
            mma_bf16(acc[2 * np + 1], ah, bl + 2);
        }
    }

    int r0 = row0 + m0 + (lane >> 2);
    int r1 = r0 + 8;
    int c0 = wc * 64 + (lane & 3) * 2;
#pragma unroll
    for (int nt = 0; nt < 8; nt++) {
        int col = c0 + nt * 8;
        if (r0 < NN)
            *reinterpret_cast<__half2*>(&g_hb[(size_t)r0 * HH + col]) =
                __floats2half2_rn(acc[nt][0], acc[nt][1]);
        if (r1 < NN)
            *reinterpret_cast<__half2*>(&g_hb[(size_t)r1 * HH + col]) =
                __floats2half2_rn(acc[nt][2], acc[nt][3]);
    }
}

// ---------------------------------------------------------------- GEMM 2/3
#define SM2_A0 0
#define SM2_A1 (A_TILE_B)
#define SM2_BH (2 * A_TILE_B)
#define SM2_BL (2 * A_TILE_B + B_TILE_B)
#define SM2_TOTAL (2 * A_TILE_B + 2 * B_TILE_B)

__global__ void __launch_bounds__(256, 2)
k_gemm23(const __half* __restrict__ Wh, const __half* __restrict__ Wl, int two_term) {
    extern __shared__ __align__(16) char smem[];
    uint32_t sb = smem_u32(smem);
    int tid  = threadIdx.x;
    int wid  = tid >> 5;
    int lane = tid & 31;

    {
        const uint4* gh = reinterpret_cast<const uint4*>(Wh);
        uint4* shv = reinterpret_cast<uint4*>(smem + SM2_BH);
        for (int i = tid; i < B_TILE_B / 16; i += 256) shv[i] = gh[i];
        if (two_term) {
            const uint4* gl = reinterpret_cast<const uint4*>(Wl);
            uint4* slv = reinterpret_cast<uint4*>(smem + SM2_BL);
            for (int i = tid; i < B_TILE_B / 16; i += 256) slv[i] = gl[i];
        }
    }

    auto stageA = [&](int tile, int bufsel) {
        int row0 = tile * 64;
        char* dstb = smem + (bufsel ? SM2_A1 : SM2_A0);
        const __half* A16 = (const __half*)h_hb;
        for (int idx = tid; idx < 64 * 32; idx += 256) {
            int r  = idx >> 5;
            int k4 = (idx & 31) * 4;
            int grow = row0 + r;
            uint2 v = make_uint2(0u, 0u);
            if (grow < NN)
                v = *reinterpret_cast<const uint2*>(A16 + (size_t)grow * HH + k4);
            *reinterpret_cast<uint2*>(dstb + (uint32_t)(r * LDA + k4) * 2) = v;
        }
    };

    int wr = wid & 3;
    int wc = wid >> 2;
    int m0 = wr * 16;
    uint32_t a_off = (uint32_t)((m0 + (lane & 15)) * LDA + ((lane >> 4) << 3)) * 2;
    uint32_t b_off = (uint32_t)(((lane & 7) + ((lane >> 1) & 8)) * LDA + (lane & 8)) * 2;

    int t0 = blockIdx.x;
    if (t0 < NTILES) stageA(t0, 0);
    __syncthreads();

    int buf = 0;
    for (int t = t0; t < NTILES; t += gridDim.x, buf ^= 1) {
        int nxt = t + gridDim.x;
        if (nxt < NTILES) stageA(nxt, buf ^ 1);

        uint32_t abase = sb + (buf ? SM2_A1 : SM2_A0) + a_off;
        float acc[8][4];
#pragma unroll
        for (int i = 0; i < 8; i++)
#pragma unroll
            for (int j = 0; j < 4; j++) acc[i][j] = 0.f;

#pragma unroll
        for (int ks = 0; ks < 8; ks++) {
            int k0 = ks * 16;
            uint32_t a[4];
            ldsm4(a, abase + k0 * 2);
#pragma unroll
            for (int np = 0; np < 4; np++) {
                uint32_t bh[4];
                uint32_t bo = (uint32_t)((wc * 64 + np * 16) * LDA + k0) * 2 + b_off;
                ldsm4(bh, sb + SM2_BH + bo);
                mma_f16(acc[2 * np],     a, bh);
                mma_f16(acc[2 * np + 1], a, bh + 2);
                if (two_term) {
                    uint32_t bl[4];
                    ldsm4(bl, sb + SM2_BL + bo);
                    mma_f16(acc[2 * np],     a, bl);
                    mma_f16(acc[2 * np + 1], a, bl + 2);
                }
            }
        }

        int row0 = t * 64;
        int r0 = row0 + m0 + (lane >> 2);
        int r1 = r0 + 8;
        float s0 = (r0 < NN) ? d_dinv[r0] : 0.f;
        float s1 = (r1 < NN) ? d_dinv[r1] : 0.f;
        int c0 = wc * 64 + (lane & 3) * 2;
#pragma unroll
        for (int nt = 0; nt < 8; nt++) {
            int col = c0 + nt * 8;
            if (r0 < NN)
                *reinterpret_cast<__half2*>(&g_hb[(size_t)r0 * HH + col]) =
                    __floats2half2_rn(acc[nt][0] * s0, acc[nt][1] * s0);
            if (r1 < NN)
                *reinterpret_cast<__half2*>(&g_hb[(size_t)r1 * HH + col]) =
                    __floats2half2_rn(acc[nt][2] * s1, acc[nt][3] * s1);
        }
        __syncthreads();
    }
}

// ---------------------------------------------------------------- aggregation
// 2 nodes per warp: half-warp (16 lanes) per node, lane loads uint4 (8 fp16 cols).
__global__ void k_agg(const float* __restrict__ x, const float* __restrict__ bias,
                      float* __restrict__ outp, int relu, int to_out, int pre_scaled) {
    int gtid = blockIdx.x * blockDim.x + threadIdx.x;
    int warp = gtid >> 5;
    int lane = gtid & 31;
    int half = lane >> 4;
    int l16  = lane & 15;
    int node = warp * 2 + half;
    if (node >= NN) return;

    const uint4* g4 = reinterpret_cast<const uint4*>(g_hb);   // 16 uint4 per row
    size_t base = (size_t)node * 16;
    float dv = d_dinv[node];

    float acc[8];
    {
        uint4 sv = g4[base + l16];
        float selfs = pre_scaled ? 1.f : dv;
        float2 p0 = __half22float2(*reinterpret_cast<__half2*>(&sv.x));
        float2 p1 = __half22float2(*reinterpret_cast<__half2*>(&sv.y));
        float2 p2 = __half22float2(*reinterpret_cast<__half2*>(&sv.z));
        float2 p3 = __half22float2(*reinterpret_cast<__half2*>(&sv.w));
        acc[0] = p0.x * selfs; acc[1] = p0.y * selfs;
        acc[2] = p1.x * selfs; acc[3] = p1.y * selfs;
        acc[4] = p2.x * selfs; acc[5] = p2.y * selfs;
        acc[6] = p3.x * selfs; acc[7] = p3.y * selfs;
    }

#define ACCV(v, d) { \
    float2 q0 = __half22float2(*reinterpret_cast<__half2*>(&(v).x)); \
    float2 q1 = __half22float2(*reinterpret_cast<__half2*>(&(v).y)); \
    float2 q2 = __half22float2(*reinterpret_cast<__half2*>(&(v).z)); \
    float2 q3 = __half22float2(*reinterpret_cast<__half2*>(&(v).w)); \
    acc[0] = fmaf((d), q0.x, acc[0]); acc[1] = fmaf((d), q0.y, acc[1]); \
    acc[2] = fmaf((d), q1.x, acc[2]); acc[3] = fmaf((d), q1.y, acc[3]); \
    acc[4] = fmaf((d), q2.x, acc[4]); acc[5] = fmaf((d), q2.y, acc[5]); \
    acc[6] = fmaf((d), q3.x, acc[6]); acc[7] = fmaf((d), q3.y, acc[7]); }

    int e0 = d_rowstart[node];
    int e1 = d_rowstart[node + 1];
    int e = e0;
    if (pre_scaled) {
        for (; e + 4 <= e1; e += 4) {
            int s0 = d_srcs[e], s1 = d_srcs[e + 1], s2 = d_srcs[e + 2], s3 = d_srcs[e + 3];
            uint4 v0 = g4[(size_t)s0 * 16 + l16];
            uint4 v1 = g4[(size_t)s1 * 16 + l16];
            uint4 v2 = g4[(size_t)s2 * 16 + l16];
            uint4 v3 = g4[(size_t)s3 * 16 + l16];
            ACCV(v0, 1.f) ACCV(v1, 1.f) ACCV(v2, 1.f) ACCV(v3, 1.f)
        }
        for (; e < e1; ++e) {
            uint4 v = g4[(size_t)d_srcs[e] * 16 + l16];
            ACCV(v, 1.f)
        }
    } else {
        for (; e + 4 <= e1; e += 4) {
            int s0 = d_srcs[e], s1 = d_srcs[e + 1], s2 = d_srcs[e + 2], s3 = d_srcs[e + 3];
            float d0 = d_dinv[s0], d1 = d_dinv[s1], d2 = d_dinv[s2], d3 = d_dinv[s3];
            uint4 v0 = g4[(size_t)s0 * 16 + l16];
            uint4 v1 = g4[(size_t)s1 * 16 + l16];
            uint4 v2 = g4[(size_t)s2 * 16 + l16];
            uint4 v3 = g4[(size_t)s3 * 16 + l16];
            ACCV(v0, d0) ACCV(v1, d1) ACCV(v2, d2) ACCV(v3, d3)
        }
        for (; e < e1; ++e) {
            int s = d_srcs[e];
            float d = d_dinv[s];
            uint4 v = g4[(size_t)s * 16 + l16];
            ACCV(v, d)
        }
    }
#undef ACCV

    size_t cbase = (size_t)node * HH + l16 * 8;
    float4 bb0 = *reinterpret_cast<const float4*>(bias + l16 * 8);
    float4 bb1 = *reinterpret_cast<const float4*>(bias + l16 * 8 + 4);
    float4 xv0 = *reinterpret_cast<const float4*>(x + cbase);
    float4 xv1 = *reinterpret_cast<const float4*>(x + cbase + 4);
    float o[8];
    o[0] = fmaf(dv, acc[0], bb0.x + xv0.x);
    o[1] = fmaf(dv, acc[1], bb0.y + xv0.y);
    o[2] = fmaf(dv, acc[2], bb0.z + xv0.z);
    o[3] = fmaf(dv, acc[3], bb0.w + xv0.w);
    o[4] = fmaf(dv, acc[4], bb1.x + xv1.x);
    o[5] = fmaf(dv, acc[5], bb1.y + xv1.y);
    o[6] = fmaf(dv, acc[6], bb1.z + xv1.z);
    o[7] = fmaf(dv, acc[7], bb1.w + xv1.w);
    if (relu) {
#pragma unroll
        for (int j = 0; j < 8; j++) o[j] = fmaxf(o[j], 0.f);
    }
    if (to_out) {
        *reinterpret_cast<float4*>(outp + cbase)     = make_float4(o[0], o[1], o[2], o[3]);
        *reinterpret_cast<float4*>(outp + cbase + 4) = make_float4(o[4], o[5], o[6], o[7]);
    } else {
        uint4 pk;
        *reinterpret_cast<__half2*>(&pk.x) = __floats2half2_rn(o[0], o[1]);
        *reinterpret_cast<__half2*>(&pk.y) = __floats2half2_rn(o[2], o[3]);
        *reinterpret_cast<__half2*>(&pk.z) = __floats2half2_rn(o[4], o[5]);
        *reinterpret_cast<__half2*>(&pk.w) = __floats2half2_rn(o[6], o[7]);
        *reinterpret_cast<uint4*>(&h_hb[cbase]) = pk;
    }
}

// ---------------------------------------------------------------- launch
extern "C" void kernel_launch(void* const* d_in, const int* in_sizes, int n_in,
                              void* d_out, int out_size) {
    const float* x   = (const float*)d_in[0];
    const int*   src = (const int*)  d_in[1];
    const int*   dst = (const int*)  d_in[2];
    const float* W1  = (const float*)d_in[3];
    const float* b1  = (const float*)d_in[4];
    const float* W2  = (const float*)d_in[5];
    const float* b2  = (const float*)d_in[6];
    float* out = (float*)d_out;

    (void)in_sizes; (void)n_in; (void)out_size;

    static int inited = 0;
    static cudaStream_t s1;
    static cudaEvent_t evFork, evJoin;
    if (!inited) {
        cudaFuncSetAttribute(k_gemm1,  cudaFuncAttributeMaxDynamicSharedMemorySize, SM1_TOTAL);
        cudaFuncSetAttribute(k_gemm23, cudaFuncAttributeMaxDynamicSharedMemorySize, SM2_TOTAL);
        cudaStreamCreateWithFlags(&s1, cudaStreamNonBlocking);
        cudaEventCreateWithFlags(&evFork, cudaEventDisableTiming);
        cudaEventCreateWithFlags(&evJoin, cudaEventDisableTiming);
        inited = 1;
    }

    __nv_bfloat16 *w1h, *w1l;
    __half *w2h, *w2l;
    cudaGetSymbolAddress((void**)&w1h, d_W1h);
    cudaGetSymbolAddress((void**)&w1l, d_W1l);
    cudaGetSymbolAddress((void**)&w2h, d_W2h);
    cudaGetSymbolAddress((void**)&w2l, d_W2l);

    const int gemm23_grid = 296;              // persistent: 2 CTAs x 148 SMs
    const int agg_grid = (((NN + 1) / 2) * 32 + 255) / 256;   // 2 nodes/warp

    // Fork: CSR build + W2 prep on s1; W1 prep + GEMM1 on main stream.
    cudaEventRecord(evFork, 0);
    cudaStreamWaitEvent(s1, evFork, 0);

    k_zero_deg<<<(NN / 4 + 255) / 256, 256, 0, s1>>>();
    k_count   <<<(EE / 4 + 255) / 256, 256, 0, s1>>>(dst);
    k_scan    <<<1, 1024, 0, s1>>>();
    k_scatter <<<(EE / 4 + 255) / 256, 256, 0, s1>>>(src, dst);
    k_prepw_f16<<<64, 256, 0, s1>>>(W2, w2h, w2l);
    cudaEventRecord(evJoin, s1);

    k_prepw_bf16<<<64, 256>>>(W1, w1h, w1l);
    k_gemm1<<<NTILES, 256, SM1_TOTAL>>>(x, w1h, w1l);   // overlaps CSR

    cudaStreamWaitEvent(0, evJoin, 0);

    // layer 1 (g unscaled -> agg applies dinv[src])
    k_agg<<<agg_grid, 256>>>(x, b1, out, 1, 0, /*pre_scaled=*/0);
    // layer 2 (full 2-term)
    k_gemm23<<<gemm23_grid, 256, SM2_TOTAL>>>(w2h, w2l, /*two_term=*/1);
    k_agg<<<agg_grid, 256>>>(x, b2, out, 1, 0, /*pre_scaled=*/1);
    // layer 3 (1-term: last layer, error does not propagate)
    k_gemm23<<<gemm23_grid, 256, SM2_TOTAL>>>(w2h, w2l, /*two_term=*/0);
    k_agg<<<agg_grid, 256>>>(x, b2, out, 0, 1, /*pre_scaled=*/1);
}

// round 17
// speedup vs baseline: 1.6489x; 1.1715x over previous
#include <cuda_runtime.h>
#include <cuda_bf16.h>
#include <cuda_fp16.h>
#include <cstdint>

#define NN 100000
#define EE 1600000
#define HH 128
#define NTILES ((NN + 63) / 64)      // 1563

typedef unsigned long long ull;

// ---- scratch (device globals) ----
static __device__ __half g_hb[(size_t)NN * HH];   // GEMM output, fp16
static __device__ __half h_hb[(size_t)NN * HH];   // layer activations (relu'd), fp16
static __device__ float  d_dinv[NN];
static __device__ int    d_deg[NN];
static __device__ int    d_rowstart[NN + 1];
static __device__ int    d_cursor[NN];
static __device__ int    d_srcs[EE];
#define LDA 136
static __device__ __nv_bfloat16 d_W1h[128 * LDA], d_W1l[128 * LDA];
static __device__ __half d_W2h[128 * LDA], d_W2l[128 * LDA];

// ---------------------------------------------------------------- CSR build
__global__ void k_zero_deg() {
    int i = blockIdx.x * blockDim.x + threadIdx.x;
    if (i < NN / 4) reinterpret_cast<int4*>(d_deg)[i] = make_int4(0, 0, 0, 0);
}

__global__ void k_count(const int* __restrict__ dst) {
    int i = blockIdx.x * blockDim.x + threadIdx.x;
    if (i >= EE / 4) return;
    int4 d = reinterpret_cast<const int4*>(dst)[i];
    atomicAdd(&d_deg[d.x], 1);
    atomicAdd(&d_deg[d.y], 1);
    atomicAdd(&d_deg[d.z], 1);
    atomicAdd(&d_deg[d.w], 1);
}

__global__ void k_scan() {
    __shared__ int warpsum[32];
    int tid  = threadIdx.x;
    int lane = tid & 31;
    int wid  = tid >> 5;
    int running = 0;
    for (int base = 0; base < NN; base += 4096) {
        int gi = base + tid * 4;
        int4 v = make_int4(0, 0, 0, 0);
        if (gi + 3 < NN) {
            v = *reinterpret_cast<const int4*>(&d_deg[gi]);
        } else {
            if (gi     < NN) v.x = d_deg[gi];
            if (gi + 1 < NN) v.y = d_deg[gi + 1];
            if (gi + 2 < NN) v.z = d_deg[gi + 2];
            if (gi + 3 < NN) v.w = d_deg[gi + 3];
        }
        int t = v.x + v.y + v.z + v.w;
        int inc = t;
#pragma unroll
        for (int off = 1; off < 32; off <<= 1) {
            int n = __shfl_up_sync(0xffffffffu, inc, off);
            if (lane >= off) inc += n;
        }
        if (lane == 31) warpsum[wid] = inc;
        __syncthreads();
        if (wid == 0) {
            int wi = warpsum[lane];
#pragma unroll
            for (int off = 1; off < 32; off <<= 1) {
                int n = __shfl_up_sync(0xffffffffu, wi, off);
                if (lane >= off) wi += n;
            }
            warpsum[lane] = wi;
        }
        __syncthreads();
        int warpoff = (wid > 0) ? warpsum[wid - 1] : 0;
        int excl = running + warpoff + inc - t;
        if (gi < NN) {
            d_rowstart[gi] = excl; d_cursor[gi] = excl;
            d_dinv[gi] = rsqrtf((float)(v.x + 1)); excl += v.x;
        }
        if (gi + 1 < NN) {
            d_rowstart[gi + 1] = excl; d_cursor[gi + 1] = excl;
            d_dinv[gi + 1] = rsqrtf((float)(v.y + 1)); excl += v.y;
        }
        if (gi + 2 < NN) {
            d_rowstart[gi + 2] = excl; d_cursor[gi + 2] = excl;
            d_dinv[gi + 2] = rsqrtf((float)(v.z + 1)); excl += v.z;
        }
        if (gi + 3 < NN) {
            d_rowstart[gi + 3] = excl; d_cursor[gi + 3] = excl;
            d_dinv[gi + 3] = rsqrtf((float)(v.w + 1));
        }
        int tot = warpsum[31];
        __syncthreads();
        running += tot;
    }
    if (tid == 0) d_rowstart[NN] = EE;
}

__global__ void k_scatter(const int* __restrict__ src, const int* __restrict__ dst) {
    int i = blockIdx.x * blockDim.x + threadIdx.x;
    if (i >= EE / 4) return;
    int4 d = reinterpret_cast<const int4*>(dst)[i];
    int4 s = reinterpret_cast<const int4*>(src)[i];
    d_srcs[atomicAdd(&d_cursor[d.x], 1)] = s.x;
    d_srcs[atomicAdd(&d_cursor[d.y], 1)] = s.y;
    d_srcs[atomicAdd(&d_cursor[d.z], 1)] = s.z;
    d_srcs[atomicAdd(&d_cursor[d.w], 1)] = s.w;
}

// ---------------------------------------------------------------- W pre-convert
__global__ void k_prepw_bf16(const float* __restrict__ W,
                             __nv_bfloat16* __restrict__ oh, __nv_bfloat16* __restrict__ ol) {
    int idx = blockIdx.x * blockDim.x + threadIdx.x;
    if (idx >= 128 * 128) return;
    int k = idx >> 7;
    int n = idx & 127;
    float v = W[(size_t)k * HH + n];
    __nv_bfloat16 h = __float2bfloat16_rn(v);
    __nv_bfloat16 l = __float2bfloat16_rn(v - __bfloat162float(h));
    oh[n * LDA + k] = h;
    ol[n * LDA + k] = l;
}

__global__ void k_prepw_f16(const float* __restrict__ W,
                            __half* __restrict__ oh, __half* __restrict__ ol) {
    int idx = blockIdx.x * blockDim.x + threadIdx.x;
    if (idx >= 128 * 128) return;
    int k = idx >> 7;
    int n = idx & 127;
    float v = W[(size_t)k * HH + n];
    __half h = __float2half_rn(v);
    __half l = __float2half_rn(v - __half2float(h));
    oh[n * LDA + k] = h;
    ol[n * LDA + k] = l;
}

// ---------------------------------------------------------------- mma utils
__device__ __forceinline__ uint32_t smem_u32(const void* p) {
    uint32_t a;
    asm("{ .reg .u64 t; cvta.to.shared.u64 t, %1; cvt.u32.u64 %0, t; }" : "=r"(a) : "l"(p));
    return a;
}
__device__ __forceinline__ void ldsm4(uint32_t* r, uint32_t addr) {
    asm volatile("ldmatrix.sync.aligned.m8n8.x4.shared.b16 {%0,%1,%2,%3}, [%4];"
                 : "=r"(r[0]), "=r"(r[1]), "=r"(r[2]), "=r"(r[3]) : "r"(addr));
}
__device__ __forceinline__ void mma_bf16(float* d, const uint32_t* a, const uint32_t* b) {
    asm volatile(
        "mma.sync.aligned.m16n8k16.row.col.f32.bf16.bf16.f32 "
        "{%0,%1,%2,%3}, {%4,%5,%6,%7}, {%8,%9}, {%0,%1,%2,%3};"
        : "+f"(d[0]), "+f"(d[1]), "+f"(d[2]), "+f"(d[3])
        : "r"(a[0]), "r"(a[1]), "r"(a[2]), "r"(a[3]), "r"(b[0]), "r"(b[1]));
}
__device__ __forceinline__ void mma_f16(float* d, const uint32_t* a, const uint32_t* b) {
    asm volatile(
        "mma.sync.aligned.m16n8k16.row.col.f32.f16.f16.f32 "
        "{%0,%1,%2,%3}, {%4,%5,%6,%7}, {%8,%9}, {%0,%1,%2,%3};"
        : "+f"(d[0]), "+f"(d[1]), "+f"(d[2]), "+f"(d[3])
        : "r"(a[0]), "r"(a[1]), "r"(a[2]), "r"(a[3]), "r"(b[0]), "r"(b[1]));
}
__device__ __forceinline__ uint32_t pack_hi(float x, float y, uint32_t& lo) {
    __nv_bfloat16 h0 = __float2bfloat16_rn(x);
    __nv_bfloat16 h1 = __float2bfloat16_rn(y);
    __nv_bfloat16 l0 = __float2bfloat16_rn(x - __bfloat162float(h0));
    __nv_bfloat16 l1 = __float2bfloat16_rn(y - __bfloat162float(h1));
    lo = (uint32_t)__bfloat16_as_ushort(l0) | ((uint32_t)__bfloat16_as_ushort(l1) << 16);
    return (uint32_t)__bfloat16_as_ushort(h0) | ((uint32_t)__bfloat16_as_ushort(h1) << 16);
}

#define A_TILE_B (64 * LDA * 2)
#define B_TILE_B (128 * LDA * 2)

// ---------------------------------------------------------------- GEMM layer 1
// Persistent: B hi/lo staged once; single A buffer (hi/lo); tile loop.
#define SM1_AH 0
#define SM1_AL (A_TILE_B)
#define SM1_BH (2 * A_TILE_B)
#define SM1_BL (2 * A_TILE_B + B_TILE_B)
#define SM1_TOTAL (2 * A_TILE_B + 2 * B_TILE_B)   // 104448

__global__ void __launch_bounds__(256, 2)
k_gemm1(const float* __restrict__ xf32,
        const __nv_bfloat16* __restrict__ Wh, const __nv_bfloat16* __restrict__ Wl) {
    extern __shared__ __align__(16) char smem[];
    uint32_t sb = smem_u32(smem);
    int tid  = threadIdx.x;
    int wid  = tid >> 5;
    int lane = tid & 31;

    // stage B once
    {
        const uint4* gh = reinterpret_cast<const uint4*>(Wh);
        const uint4* gl = reinterpret_cast<const uint4*>(Wl);
        uint4* shv = reinterpret_cast<uint4*>(smem + SM1_BH);
        uint4* slv = reinterpret_cast<uint4*>(smem + SM1_BL);
        for (int i = tid; i < B_TILE_B / 16; i += 256) {
            shv[i] = gh[i];
            slv[i] = gl[i];
        }
    }

    int wr = wid & 3;
    int wc = wid >> 2;
    int m0 = wr * 16;
    uint32_t a_off = (uint32_t)((m0 + (lane & 15)) * LDA + ((lane >> 4) << 3)) * 2;
    uint32_t b_off = (uint32_t)(((lane & 7) + ((lane >> 1) & 8)) * LDA + (lane & 8)) * 2;

    for (int t = blockIdx.x; t < NTILES; t += gridDim.x) {
        int row0 = t * 64;
        __syncthreads();   // protect A buffer from previous iteration's readers
        // stage A (fp32 -> bf16 hi/lo)
        for (int idx = tid; idx < 64 * 64; idx += 256) {
            int r  = idx >> 6;
            int kp = idx & 63;
            int grow = row0 + r;
            float2 v = make_float2(0.f, 0.f);
            if (grow < NN)
                v = *reinterpret_cast<const float2*>(xf32 + (size_t)grow * HH + kp * 2);
            uint32_t lo, hi = pack_hi(v.x, v.y, lo);
            uint32_t off = (uint32_t)(r * LDA + kp * 2) * 2;
            *reinterpret_cast<uint32_t*>(smem + SM1_AH + off) = hi;
            *reinterpret_cast<uint32_t*>(smem + SM1_AL + off) = lo;
        }
        __syncthreads();

        float acc[8][4];
#pragma unroll
        for (int i = 0; i < 8; i++)
#pragma unroll
            for (int j = 0; j < 4; j++) acc[i][j] = 0.f;

#pragma unroll
        for (int ks = 0; ks < 8; ks++) {
            int k0 = ks * 16;
            uint32_t ah[4], al[4];
            ldsm4(ah, sb + SM1_AH + a_off + k0 * 2);
            ldsm4(al, sb + SM1_AL + a_off + k0 * 2);
#pragma unroll
            for (int np = 0; np < 4; np++) {
                uint32_t bh[4], bl[4];
                uint32_t bo = (uint32_t)((wc * 64 + np * 16) * LDA + k0) * 2 + b_off;
                ldsm4(bh, sb + SM1_BH + bo);
                ldsm4(bl, sb + SM1_BL + bo);
                mma_bf16(acc[2 * np],     ah, bh);
                mma_bf16(acc[2 * np + 1], ah, bh + 2);
                mma_bf16(acc[2 * np],     al, bh);
                mma_bf16(acc[2 * np + 1], al, bh + 2);
                mma_bf16(acc[2 * np],     ah, bl);
                mma_bf16(acc[2 * np + 1], ah, bl + 2);
            }
        }

        int r0 = row0 + m0 + (lane >> 2);
        int r1 = r0 + 8;
        int c0 = wc * 64 + (lane & 3) * 2;
#pragma unroll
        for (int nt = 0; nt < 8; nt++) {
            int col = c0 + nt * 8;
            if (r0 < NN)
                *reinterpret_cast<__half2*>(&g_hb[(size_t)r0 * HH + col]) =
                    __floats2half2_rn(acc[nt][0], acc[nt][1]);
            if (r1 < NN)
                *reinterpret_cast<__half2*>(&g_hb[(size_t)r1 * HH + col]) =
                    __floats2half2_rn(acc[nt][2], acc[nt][3]);
        }
    }
}

// ---------------------------------------------------------------- GEMM 2/3
#define SM2_A0 0
#define SM2_A1 (A_TILE_B)
#define SM2_BH (2 * A_TILE_B)
#define SM2_BL (2 * A_TILE_B + B_TILE_B)
#define SM2_TOTAL (2 * A_TILE_B + 2 * B_TILE_B)

__global__ void __launch_bounds__(256, 2)
k_gemm23(const __half* __restrict__ Wh, const __half* __restrict__ Wl, int two_term) {
    extern __shared__ __align__(16) char smem[];
    uint32_t sb = smem_u32(smem);
    int tid  = threadIdx.x;
    int wid  = tid >> 5;
    int lane = tid & 31;

    {
        const uint4* gh = reinterpret_cast<const uint4*>(Wh);
        uint4* shv = reinterpret_cast<uint4*>(smem + SM2_BH);
        for (int i = tid; i < B_TILE_B / 16; i += 256) shv[i] = gh[i];
        if (two_term) {
            const uint4* gl = reinterpret_cast<const uint4*>(Wl);
            uint4* slv = reinterpret_cast<uint4*>(smem + SM2_BL);
            for (int i = tid; i < B_TILE_B / 16; i += 256) slv[i] = gl[i];
        }
    }

    auto stageA = [&](int tile, int bufsel) {
        int row0 = tile * 64;
        char* dstb = smem + (bufsel ? SM2_A1 : SM2_A0);
        const __half* A16 = (const __half*)h_hb;
        for (int idx = tid; idx < 64 * 32; idx += 256) {
            int r  = idx >> 5;
            int k4 = (idx & 31) * 4;
            int grow = row0 + r;
            uint2 v = make_uint2(0u, 0u);
            if (grow < NN)
                v = *reinterpret_cast<const uint2*>(A16 + (size_t)grow * HH + k4);
            *reinterpret_cast<uint2*>(dstb + (uint32_t)(r * LDA + k4) * 2) = v;
        }
    };

    int wr = wid & 3;
    int wc = wid >> 2;
    int m0 = wr * 16;
    uint32_t a_off = (uint32_t)((m0 + (lane & 15)) * LDA + ((lane >> 4) << 3)) * 2;
    uint32_t b_off = (uint32_t)(((lane & 7) + ((lane >> 1) & 8)) * LDA + (lane & 8)) * 2;

    int t0 = blockIdx.x;
    if (t0 < NTILES) stageA(t0, 0);
    __syncthreads();

    int buf = 0;
    for (int t = t0; t < NTILES; t += gridDim.x, buf ^= 1) {
        int nxt = t + gridDim.x;
        if (nxt < NTILES) stageA(nxt, buf ^ 1);

        uint32_t abase = sb + (buf ? SM2_A1 : SM2_A0) + a_off;
        float acc[8][4];
#pragma unroll
        for (int i = 0; i < 8; i++)
#pragma unroll
            for (int j = 0; j < 4; j++) acc[i][j] = 0.f;

#pragma unroll
        for (int ks = 0; ks < 8; ks++) {
            int k0 = ks * 16;
            uint32_t a[4];
            ldsm4(a, abase + k0 * 2);
#pragma unroll
            for (int np = 0; np < 4; np++) {
                uint32_t bh[4];
                uint32_t bo = (uint32_t)((wc * 64 + np * 16) * LDA + k0) * 2 + b_off;
                ldsm4(bh, sb + SM2_BH + bo);
                mma_f16(acc[2 * np],     a, bh);
                mma_f16(acc[2 * np + 1], a, bh + 2);
                if (two_term) {
                    uint32_t bl[4];
                    ldsm4(bl, sb + SM2_BL + bo);
                    mma_f16(acc[2 * np],     a, bl);
                    mma_f16(acc[2 * np + 1], a, bl + 2);
                }
            }
        }

        int row0 = t * 64;
        int r0 = row0 + m0 + (lane >> 2);
        int r1 = r0 + 8;
        float s0 = (r0 < NN) ? d_dinv[r0] : 0.f;
        float s1 = (r1 < NN) ? d_dinv[r1] : 0.f;
        int c0 = wc * 64 + (lane & 3) * 2;
#pragma unroll
        for (int nt = 0; nt < 8; nt++) {
            int col = c0 + nt * 8;
            if (r0 < NN)
                *reinterpret_cast<__half2*>(&g_hb[(size_t)r0 * HH + col]) =
                    __floats2half2_rn(acc[nt][0] * s0, acc[nt][1] * s0);
            if (r1 < NN)
                *reinterpret_cast<__half2*>(&g_hb[(size_t)r1 * HH + col]) =
                    __floats2half2_rn(acc[nt][2] * s1, acc[nt][3] * s1);
        }
        __syncthreads();
    }
}

// ---------------------------------------------------------------- aggregation
// 2 nodes per warp: half-warp (16 lanes) per node, lane loads uint4 (8 fp16 cols).
__global__ void k_agg(const float* __restrict__ x, const float* __restrict__ bias,
                      float* __restrict__ outp, int relu, int to_out, int pre_scaled) {
    int gtid = blockIdx.x * blockDim.x + threadIdx.x;
    int warp = gtid >> 5;
    int lane = gtid & 31;
    int half = lane >> 4;
    int l16  = lane & 15;
    int node = warp * 2 + half;
    if (node >= NN) return;

    const uint4* g4 = reinterpret_cast<const uint4*>(g_hb);   // 16 uint4 per row
    size_t base = (size_t)node * 16;
    float dv = d_dinv[node];

    float acc[8];
    {
        uint4 sv = g4[base + l16];
        float selfs = pre_scaled ? 1.f : dv;
        float2 p0 = __half22float2(*reinterpret_cast<__half2*>(&sv.x));
        float2 p1 = __half22float2(*reinterpret_cast<__half2*>(&sv.y));
        float2 p2 = __half22float2(*reinterpret_cast<__half2*>(&sv.z));
        float2 p3 = __half22float2(*reinterpret_cast<__half2*>(&sv.w));
        acc[0] = p0.x * selfs; acc[1] = p0.y * selfs;
        acc[2] = p1.x * selfs; acc[3] = p1.y * selfs;
        acc[4] = p2.x * selfs; acc[5] = p2.y * selfs;
        acc[6] = p3.x * selfs; acc[7] = p3.y * selfs;
    }

#define ACCV(v, d) { \
    float2 q0 = __half22float2(*reinterpret_cast<__half2*>(&(v).x)); \
    float2 q1 = __half22float2(*reinterpret_cast<__half2*>(&(v).y)); \
    float2 q2 = __half22float2(*reinterpret_cast<__half2*>(&(v).z)); \
    float2 q3 = __half22float2(*reinterpret_cast<__half2*>(&(v).w)); \
    acc[0] = fmaf((d), q0.x, acc[0]); acc[1] = fmaf((d), q0.y, acc[1]); \
    acc[2] = fmaf((d), q1.x, acc[2]); acc[3] = fmaf((d), q1.y, acc[3]); \
    acc[4] = fmaf((d), q2.x, acc[4]); acc[5] = fmaf((d), q2.y, acc[5]); \
    acc[6] = fmaf((d), q3.x, acc[6]); acc[7] = fmaf((d), q3.y, acc[7]); }

    int e0 = d_rowstart[node];
    int e1 = d_rowstart[node + 1];
    int e = e0;
    if (pre_scaled) {
        for (; e + 4 <= e1; e += 4) {
            int s0 = d_srcs[e], s1 = d_srcs[e + 1], s2 = d_srcs[e + 2], s3 = d_srcs[e + 3];
            uint4 v0 = g4[(size_t)s0 * 16 + l16];
            uint4 v1 = g4[(size_t)s1 * 16 + l16];
            uint4 v2 = g4[(size_t)s2 * 16 + l16];
            uint4 v3 = g4[(size_t)s3 * 16 + l16];
            ACCV(v0, 1.f) ACCV(v1, 1.f) ACCV(v2, 1.f) ACCV(v3, 1.f)
        }
        for (; e < e1; ++e) {
            uint4 v = g4[(size_t)d_srcs[e] * 16 + l16];
            ACCV(v, 1.f)
        }
    } else {
        for (; e + 4 <= e1; e += 4) {
            int s0 = d_srcs[e], s1 = d_srcs[e + 1], s2 = d_srcs[e + 2], s3 = d_srcs[e + 3];
            float d0 = d_dinv[s0], d1 = d_dinv[s1], d2 = d_dinv[s2], d3 = d_dinv[s3];
            uint4 v0 = g4[(size_t)s0 * 16 + l16];
            uint4 v1 = g4[(size_t)s1 * 16 + l16];
            uint4 v2 = g4[(size_t)s2 * 16 + l16];
            uint4 v3 = g4[(size_t)s3 * 16 + l16];
            ACCV(v0, d0) ACCV(v1, d1) ACCV(v2, d2) ACCV(v3, d3)
        }
        for (; e < e1; ++e) {
            int s = d_srcs[e];
            float d = d_dinv[s];
            uint4 v = g4[(size_t)s * 16 + l16];
            ACCV(v, d)
        }
    }
#undef ACCV

    size_t cbase = (size_t)node * HH + l16 * 8;
    float4 bb0 = *reinterpret_cast<const float4*>(bias + l16 * 8);
    float4 bb1 = *reinterpret_cast<const float4*>(bias + l16 * 8 + 4);
    float4 xv0 = *reinterpret_cast<const float4*>(x + cbase);
    float4 xv1 = *reinterpret_cast<const float4*>(x + cbase + 4);
    float o[8];
    o[0] = fmaf(dv, acc[0], bb0.x + xv0.x);
    o[1] = fmaf(dv, acc[1], bb0.y + xv0.y);
    o[2] = fmaf(dv, acc[2], bb0.z + xv0.z);
    o[3] = fmaf(dv, acc[3], bb0.w + xv0.w);
    o[4] = fmaf(dv, acc[4], bb1.x + xv1.x);
    o[5] = fmaf(dv, acc[5], bb1.y + xv1.y);
    o[6] = fmaf(dv, acc[6], bb1.z + xv1.z);
    o[7] = fmaf(dv, acc[7], bb1.w + xv1.w);
    if (relu) {
#pragma unroll
        for (int j = 0; j < 8; j++) o[j] = fmaxf(o[j], 0.f);
    }
    if (to_out) {
        *reinterpret_cast<float4*>(outp + cbase)     = make_float4(o[0], o[1], o[2], o[3]);
        *reinterpret_cast<float4*>(outp + cbase + 4) = make_float4(o[4], o[5], o[6], o[7]);
    } else {
        uint4 pk;
        *reinterpret_cast<__half2*>(&pk.x) = __floats2half2_rn(o[0], o[1]);
        *reinterpret_cast<__half2*>(&pk.y) = __floats2half2_rn(o[2], o[3]);
        *reinterpret_cast<__half2*>(&pk.z) = __floats2half2_rn(o[4], o[5]);
        *reinterpret_cast<__half2*>(&pk.w) = __floats2half2_rn(o[6], o[7]);
        *reinterpret_cast<uint4*>(&h_hb[cbase]) = pk;
    }
}

// ---------------------------------------------------------------- launch
extern "C" void kernel_launch(void* const* d_in, const int* in_sizes, int n_in,
                              void* d_out, int out_size) {
    const float* x   = (const float*)d_in[0];
    const int*   src = (const int*)  d_in[1];
    const int*   dst = (const int*)  d_in[2];
    const float* W1  = (const float*)d_in[3];
    const float* b1  = (const float*)d_in[4];
    const float* W2  = (const float*)d_in[5];
    const float* b2  = (const float*)d_in[6];
    float* out = (float*)d_out;

    (void)in_sizes; (void)n_in; (void)out_size;

    static int inited = 0;
    static cudaStream_t s1;
    static cudaEvent_t evFork, evJoin;
    if (!inited) {
        cudaFuncSetAttribute(k_gemm1,  cudaFuncAttributeMaxDynamicSharedMemorySize, SM1_TOTAL);
        cudaFuncSetAttribute(k_gemm23, cudaFuncAttributeMaxDynamicSharedMemorySize, SM2_TOTAL);
        cudaStreamCreateWithFlags(&s1, cudaStreamNonBlocking);
        cudaEventCreateWithFlags(&evFork, cudaEventDisableTiming);
        cudaEventCreateWithFlags(&evJoin, cudaEventDisableTiming);
        inited = 1;
    }

    __nv_bfloat16 *w1h, *w1l;
    __half *w2h, *w2l;
    cudaGetSymbolAddress((void**)&w1h, d_W1h);
    cudaGetSymbolAddress((void**)&w1l, d_W1l);
    cudaGetSymbolAddress((void**)&w2h, d_W2h);
    cudaGetSymbolAddress((void**)&w2l, d_W2l);

    const int gemm1_grid  = 296;              // persistent
    const int gemm23_grid = 296;              // persistent
    const int agg_grid = (((NN + 1) / 2) * 32 + 255) / 256;   // 2 nodes/warp

    // Fork: CSR build + W2 prep on s1; W1 prep + GEMM1 on main stream.
    cudaEventRecord(evFork, 0);
    cudaStreamWaitEvent(s1, evFork, 0);

    k_zero_deg<<<(NN / 4 + 255) / 256, 256, 0, s1>>>();
    k_count   <<<(EE / 4 + 255) / 256, 256, 0, s1>>>(dst);
    k_scan    <<<1, 1024, 0, s1>>>();
    k_scatter <<<(EE / 4 + 255) / 256, 256, 0, s1>>>(src, dst);
    k_prepw_f16<<<64, 256, 0, s1>>>(W2, w2h, w2l);
    cudaEventRecord(evJoin, s1);

    k_prepw_bf16<<<64, 256>>>(W1, w1h, w1l);
    k_gemm1<<<gemm1_grid, 256, SM1_TOTAL>>>(x, w1h, w1l);   // overlaps CSR

    cudaStreamWaitEvent(0, evJoin, 0);

    // layer 1 (g unscaled -> agg applies dinv[src])
    k_agg<<<agg_grid, 256>>>(x, b1, out, 1, 0, /*pre_scaled=*/0);
    // layer 2 (full 2-term)
    k_gemm23<<<gemm23_grid, 256, SM2_TOTAL>>>(w2h, w2l, /*two_term=*/1);
    k_agg<<<agg_grid, 256>>>(x, b2, out, 1, 0, /*pre_scaled=*/1);
    // layer 3 (1-term: last layer, error does not propagate)
    k_gemm23<<<gemm23_grid, 256, SM2_TOTAL>>>(w2h, w2l, /*two_term=*/0);
    k_agg<<<agg_grid, 256>>>(x, b2, out, 0, 1, /*pre_scaled=*/1);
}